// round 12
// baseline (speedup 1.0000x reference)
#include <cuda_runtime.h>
#include <cuda_bf16.h>
#include <cstdint>

#define NN 100000
#define NE 1600000
#define FH 128
#define CC 64
#define GB1 3126          // gemm blocks in fused kernel: ceil(NN/64)*2
#define DEGB 6250         // degree blocks: ceil(NE/256)

// ---------------- scratch ----------------
__device__ float g_h[3ll * NN * FH];                 // h1,h2,h3 (fp32)
__device__ __nv_bfloat162 g_y[(long long)NN * 64];   // Y packed bf16x2
__device__ float g_z[(long long)NN * CC];
__device__ __align__(16) float g_onorm[NN];
__device__ __align__(16) float g_inorm[NN];
__device__ __align__(16) int   g_deg[2 * NN];        // [0,NN)=indeg, [NN,2NN)=outdeg
__device__ __align__(16) int   g_rs[NN + 4];
__device__ __align__(16) int   g_cur[NN + 4];
__device__ __align__(16) int   g_perm[NE];

// ---------------- helpers ----------------
__device__ __forceinline__ uint32_t to_tf32(float x) {
    uint32_t y;
    asm("cvt.rna.tf32.f32 %0, %1;" : "=r"(y) : "f"(x));
    return y;
}
__device__ __forceinline__ float to_tf32f(float x) {
    return __uint_as_float(to_tf32(x));
}

__device__ __forceinline__ void mma_tf32(float* c, const uint32_t* a, uint32_t b0, uint32_t b1) {
    asm volatile(
        "mma.sync.aligned.m16n8k8.row.col.f32.tf32.tf32.f32 "
        "{%0,%1,%2,%3}, {%4,%5,%6,%7}, {%8,%9}, {%0,%1,%2,%3};"
        : "+f"(c[0]), "+f"(c[1]), "+f"(c[2]), "+f"(c[3])
        : "r"(a[0]), "r"(a[1]), "r"(a[2]), "r"(a[3]), "r"(b0), "r"(b1));
}

// ---------------- TF32 conv GEMM body: Y[N,128] = X @ W[128,128], optional row-scale by onorm ----------------
// M=64 x N=64 tile (by = N-half). 256 thr / 8 warps. Register-prefetch pipeline.
template <bool SCALE>
__device__ __forceinline__ void gemm_conv_body(const float* __restrict__ X,
                                               const float* __restrict__ W,
                                               __nv_bfloat162* __restrict__ Y,
                                               int bx, int by) {
    __shared__ float As[64][36];
    __shared__ float Ws[32][72];
    int tid = threadIdx.x;
    int warp = tid >> 5, lane = tid & 31;
    int gid = lane >> 2, tig = lane & 3;
    int m0 = (warp & 3) * 16;
    int ng = warp >> 2;
    int row0 = bx * 64;
    int nh = by * 64;

    float acc[4][4];
#pragma unroll
    for (int i = 0; i < 4; i++)
#pragma unroll
        for (int j = 0; j < 4; j++) acc[i][j] = 0.f;

    float4 pa[2], pw[2];

    auto ldA = [&](int k0) {
#pragma unroll
        for (int u = 0; u < 2; u++) {
            int i = tid + u * 256;
            int m = i >> 3, kq = (i & 7) * 4;
            int r = row0 + m;
            pa[u] = (r < NN) ? *(const float4*)&X[r * 128 + k0 + kq]
                             : make_float4(0.f, 0.f, 0.f, 0.f);
        }
    };
    auto ldW = [&](int k0) {
#pragma unroll
        for (int u = 0; u < 2; u++) {
            int i = tid + u * 256;
            int k = i >> 4, nq = (i & 15) * 4;
            pw[u] = *(const float4*)&W[(k0 + k) * 128 + nh + nq];
        }
    };
    auto stAW = [&]() {
#pragma unroll
        for (int u = 0; u < 2; u++) {
            int i = tid + u * 256;
            int m = i >> 3, kq = (i & 7) * 4;
            As[m][kq + 0] = to_tf32f(pa[u].x);
            As[m][kq + 1] = to_tf32f(pa[u].y);
            As[m][kq + 2] = to_tf32f(pa[u].z);
            As[m][kq + 3] = to_tf32f(pa[u].w);
            int k = i >> 4, nq = (i & 15) * 4;
            Ws[k][nq + 0] = to_tf32f(pw[u].x);
            Ws[k][nq + 1] = to_tf32f(pw[u].y);
            Ws[k][nq + 2] = to_tf32f(pw[u].z);
            Ws[k][nq + 3] = to_tf32f(pw[u].w);
        }
    };

    ldA(0); ldW(0);
    stAW();
    __syncthreads();

    for (int kc = 0; kc < 4; kc++) {
        if (kc < 3) { ldA((kc + 1) * 32); ldW((kc + 1) * 32); }
#pragma unroll
        for (int ks = 0; ks < 4; ks++) {
            int kk = ks * 8;
            uint32_t a[4];
            a[0] = __float_as_uint(As[m0 + gid][kk + tig]);
            a[1] = __float_as_uint(As[m0 + gid + 8][kk + tig]);
            a[2] = __float_as_uint(As[m0 + gid][kk + tig + 4]);
            a[3] = __float_as_uint(As[m0 + gid + 8][kk + tig + 4]);
#pragma unroll
            for (int nt = 0; nt < 4; nt++) {
                uint32_t b0 = __float_as_uint(Ws[kk + tig][ng * 32 + nt * 8 + gid]);
                uint32_t b1 = __float_as_uint(Ws[kk + tig + 4][ng * 32 + nt * 8 + gid]);
                mma_tf32(acc[nt], a, b0, b1);
            }
        }
        __syncthreads();
        if (kc < 3) {
            stAW();
            __syncthreads();
        }
    }

    int r0 = row0 + m0 + gid;
    int r1 = r0 + 8;
    float on0 = 1.f, on1 = 1.f;
    if (SCALE) {
        if (r0 < NN) on0 = __ldg(&g_onorm[r0]);
        if (r1 < NN) on1 = __ldg(&g_onorm[r1]);
    }
#pragma unroll
    for (int nt = 0; nt < 4; nt++) {
        int cp = (nh + ng * 32 + nt * 8 + tig * 2) >> 1;
        if (r0 < NN) Y[r0 * 64 + cp] = __float22bfloat162_rn(make_float2(acc[nt][0] * on0, acc[nt][1] * on0));
        if (r1 < NN) Y[r1 * 64 + cp] = __float22bfloat162_rn(make_float2(acc[nt][2] * on1, acc[nt][3] * on1));
    }
}

// ---------------- fused: layer-1 GEMM (unscaled) + degree counting ----------------
__global__ __launch_bounds__(256) void k_fused1(const int* __restrict__ src,
                                                const int* __restrict__ dst,
                                                const float* __restrict__ X,
                                                const float* __restrict__ W,
                                                __nv_bfloat162* __restrict__ Y) {
    if (blockIdx.x < GB1) {
        gemm_conv_body<false>(X, W, Y, blockIdx.x >> 1, blockIdx.x & 1);
    } else {
        int e = (blockIdx.x - GB1) * 256 + threadIdx.x;
        if (e < NE) {
            atomicAdd(&g_deg[NN + src[e]], 1);   // outdeg
            atomicAdd(&g_deg[dst[e]], 1);        // indeg
        }
    }
}

// ---------------- conv GEMM with epilogue onorm (layers 2,3) ----------------
__global__ __launch_bounds__(256) void k_gemm_conv_tc(const float* __restrict__ X,
                                                      const float* __restrict__ W,
                                                      __nv_bfloat162* __restrict__ Y) {
    gemm_conv_body<true>(X, W, Y, blockIdx.x, blockIdx.y);
}

// ---------------- scan + norms (int4, fused) ----------------
__global__ __launch_bounds__(1024) void k_scan() {
    __shared__ int sums[1024];
    int tid = threadIdx.x;
    const int chunk = 100;
    int b = tid * chunk;
    int s = 0;
    if (b < NN) {
        const int4* p = (const int4*)(g_deg + b);
#pragma unroll 5
        for (int i = 0; i < 25; i++) {
            int4 v = p[i];
            s += v.x + v.y + v.z + v.w;
        }
    }
    sums[tid] = s;
    __syncthreads();
    for (int off = 1; off < 1024; off <<= 1) {
        int v = (tid >= off) ? sums[tid - off] : 0;
        __syncthreads();
        sums[tid] += v;
        __syncthreads();
    }
    int run = (tid == 0) ? 0 : sums[tid - 1];
    if (b < NN) {
        const int4* pi = (const int4*)(g_deg + b);
        const int4* po = (const int4*)(g_deg + NN + b);
        for (int i = 0; i < 25; i++) {
            int4 di = pi[i];
            int4 dq = po[i];
            int4 r4;
            r4.x = run; run += di.x;
            r4.y = run; run += di.y;
            r4.z = run; run += di.z;
            r4.w = run; run += di.w;
            *(int4*)(g_rs + b + i * 4) = r4;
            *(int4*)(g_cur + b + i * 4) = r4;
            float4 in4, on4;
            in4.x = di.x > 0 ? rsqrtf((float)di.x) : 0.f;
            in4.y = di.y > 0 ? rsqrtf((float)di.y) : 0.f;
            in4.z = di.z > 0 ? rsqrtf((float)di.z) : 0.f;
            in4.w = di.w > 0 ? rsqrtf((float)di.w) : 0.f;
            on4.x = dq.x > 0 ? rsqrtf((float)dq.x) : 0.f;
            on4.y = dq.y > 0 ? rsqrtf((float)dq.y) : 0.f;
            on4.z = dq.z > 0 ? rsqrtf((float)dq.z) : 0.f;
            on4.w = dq.w > 0 ? rsqrtf((float)dq.w) : 0.f;
            *(float4*)(g_inorm + b + i * 4) = in4;
            *(float4*)(g_onorm + b + i * 4) = on4;
        }
        if (b + chunk == NN) g_rs[NN] = run;
    }
}

__global__ void k_build(const int* __restrict__ src, const int* __restrict__ dst) {
    int e = blockIdx.x * blockDim.x + threadIdx.x;
    if (e < NE) {
        int p = atomicAdd(&g_cur[dst[e]], 1);
        g_perm[p] = src[e];
    }
}

// ---------------- TF32 GEMM: Z[N,64] = concat(h1,h2,h3) @ Wo[384,64] (pipelined) ----------------
__global__ __launch_bounds__(256) void k_gemm_z_tc(const float* __restrict__ Hc,
                                                   const float* __restrict__ Wo,
                                                   float* __restrict__ Z) {
    __shared__ float As[64][36];
    __shared__ float Ws[32][72];
    int tid = threadIdx.x;
    int warp = tid >> 5, lane = tid & 31;
    int gid = lane >> 2, tig = lane & 3;
    int m0 = (warp & 3) * 16;
    int ng = warp >> 2;
    int row0 = blockIdx.x * 64;

    float acc[4][4];
#pragma unroll
    for (int i = 0; i < 4; i++)
#pragma unroll
        for (int j = 0; j < 4; j++) acc[i][j] = 0.f;

    float4 pa[2], pw[2];

    auto ldA = [&](int kc) {
        int k0 = kc * 32;
        const float* Xb = Hc + (long long)(k0 >> 7) * NN * 128;
        int cb = k0 & 127;
#pragma unroll
        for (int u = 0; u < 2; u++) {
            int i = tid + u * 256;
            int m = i >> 3, kq = (i & 7) * 4;
            int r = row0 + m;
            pa[u] = (r < NN) ? *(const float4*)&Xb[r * 128 + cb + kq]
                             : make_float4(0.f, 0.f, 0.f, 0.f);
        }
    };
    auto ldW = [&](int kc) {
        int k0 = kc * 32;
#pragma unroll
        for (int u = 0; u < 2; u++) {
            int i = tid + u * 256;
            int k = i >> 4, nq = (i & 15) * 4;
            pw[u] = *(const float4*)&Wo[(k0 + k) * 64 + nq];
        }
    };
    auto stAW = [&]() {
#pragma unroll
        for (int u = 0; u < 2; u++) {
            int i = tid + u * 256;
            int m = i >> 3, kq = (i & 7) * 4;
            As[m][kq + 0] = to_tf32f(pa[u].x);
            As[m][kq + 1] = to_tf32f(pa[u].y);
            As[m][kq + 2] = to_tf32f(pa[u].z);
            As[m][kq + 3] = to_tf32f(pa[u].w);
            int k = i >> 4, nq = (i & 15) * 4;
            Ws[k][nq + 0] = to_tf32f(pw[u].x);
            Ws[k][nq + 1] = to_tf32f(pw[u].y);
            Ws[k][nq + 2] = to_tf32f(pw[u].z);
            Ws[k][nq + 3] = to_tf32f(pw[u].w);
        }
    };

    ldA(0); ldW(0);
    stAW();
    __syncthreads();

    for (int kc = 0; kc < 12; kc++) {
        if (kc < 11) { ldA(kc + 1); ldW(kc + 1); }
#pragma unroll
        for (int ks = 0; ks < 4; ks++) {
            int kk = ks * 8;
            uint32_t a[4];
            a[0] = __float_as_uint(As[m0 + gid][kk + tig]);
            a[1] = __float_as_uint(As[m0 + gid + 8][kk + tig]);
            a[2] = __float_as_uint(As[m0 + gid][kk + tig + 4]);
            a[3] = __float_as_uint(As[m0 + gid + 8][kk + tig + 4]);
#pragma unroll
            for (int nt = 0; nt < 4; nt++) {
                uint32_t b0 = __float_as_uint(Ws[kk + tig][ng * 32 + nt * 8 + gid]);
                uint32_t b1 = __float_as_uint(Ws[kk + tig + 4][ng * 32 + nt * 8 + gid]);
                mma_tf32(acc[nt], a, b0, b1);
            }
        }
        __syncthreads();
        if (kc < 11) {
            stAW();
            __syncthreads();
        }
    }

    int r0 = row0 + m0 + gid;
    int r1 = r0 + 8;
#pragma unroll
    for (int nt = 0; nt < 4; nt++) {
        int c = ng * 32 + nt * 8 + tig * 2;
        if (r0 < NN) *(float2*)&Z[r0 * 64 + c] = make_float2(acc[nt][0], acc[nt][1]);
        if (r1 < NN) *(float2*)&Z[r1 * 64 + c] = make_float2(acc[nt][2], acc[nt][3]);
    }
}

// ---------------- aggregation helpers ----------------
__device__ __forceinline__ void bf2acc(float4& a, uint2 u) {
    __nv_bfloat162 p0 = *(__nv_bfloat162*)&u.x;
    __nv_bfloat162 p1 = *(__nv_bfloat162*)&u.y;
    float2 f0 = __bfloat1622float2(p0);
    float2 f1 = __bfloat1622float2(p1);
    a.x += f0.x; a.y += f0.y; a.z += f1.x; a.w += f1.y;
}
__device__ __forceinline__ void bf2acc_on(float4& a, uint2 u, float on) {
    __nv_bfloat162 p0 = *(__nv_bfloat162*)&u.x;
    __nv_bfloat162 p1 = *(__nv_bfloat162*)&u.y;
    float2 f0 = __bfloat1622float2(p0);
    float2 f1 = __bfloat1622float2(p1);
    a.x += on * f0.x; a.y += on * f0.y; a.z += on * f1.x; a.w += on * f1.y;
}

// ---------------- agg (layers 2,3): Y pre-scaled; plain sum. int4 perm loads. ----------------
__global__ __launch_bounds__(256) void k_agg(const __nv_bfloat162* __restrict__ Y,
                                             const float* __restrict__ b,
                                             float* __restrict__ Hout) {
    int v = (blockIdx.x * 256 + threadIdx.x) >> 5;
    if (v >= NN) return;
    int lane = threadIdx.x & 31;
    int col = lane * 4;
    int pbase = lane * 2;
    int s = g_rs[v], e = g_rs[v + 1];
    float4 a0 = make_float4(0.f, 0.f, 0.f, 0.f), a1 = a0, a2 = a0, a3 = a0;

    int j = s;
    for (; j < e && (j & 3); j++)
        bf2acc(a0, __ldg((const uint2*)&Y[__ldg(&g_perm[j]) * 64 + pbase]));
    for (; j + 4 <= e; j += 4) {
        int4 p = *(const int4*)&g_perm[j];
        uint2 u0 = __ldg((const uint2*)&Y[p.x * 64 + pbase]);
        uint2 u1 = __ldg((const uint2*)&Y[p.y * 64 + pbase]);
        uint2 u2 = __ldg((const uint2*)&Y[p.z * 64 + pbase]);
        uint2 u3 = __ldg((const uint2*)&Y[p.w * 64 + pbase]);
        bf2acc(a0, u0); bf2acc(a1, u1); bf2acc(a2, u2); bf2acc(a3, u3);
    }
    for (; j < e; j++)
        bf2acc(a0, __ldg((const uint2*)&Y[__ldg(&g_perm[j]) * 64 + pbase]));

    float in = g_inorm[v];
    float4 bb = __ldg((const float4*)&b[col]);
    float4 r;
    r.x = fmaxf((a0.x + a1.x + a2.x + a3.x) * in + bb.x, 0.f);
    r.y = fmaxf((a0.y + a1.y + a2.y + a3.y) * in + bb.y, 0.f);
    r.z = fmaxf((a0.z + a1.z + a2.z + a3.z) * in + bb.z, 0.f);
    r.w = fmaxf((a0.w + a1.w + a2.w + a3.w) * in + bb.w, 0.f);
    *(float4*)&Hout[v * 128 + col] = r;
}

// ---------------- agg (layer 1): per-edge onorm (Y unscaled). int4 perm loads. ----------------
__global__ __launch_bounds__(256) void k_agg_on(const __nv_bfloat162* __restrict__ Y,
                                                const float* __restrict__ b,
                                                float* __restrict__ Hout) {
    int v = (blockIdx.x * 256 + threadIdx.x) >> 5;
    if (v >= NN) return;
    int lane = threadIdx.x & 31;
    int col = lane * 4;
    int pbase = lane * 2;
    int s = g_rs[v], e = g_rs[v + 1];
    float4 a0 = make_float4(0.f, 0.f, 0.f, 0.f), a1 = a0, a2 = a0, a3 = a0;

    int j = s;
    for (; j < e && (j & 3); j++) {
        int s0 = __ldg(&g_perm[j]);
        bf2acc_on(a0, __ldg((const uint2*)&Y[s0 * 64 + pbase]), __ldg(&g_onorm[s0]));
    }
    for (; j + 4 <= e; j += 4) {
        int4 p = *(const int4*)&g_perm[j];
        float on0 = __ldg(&g_onorm[p.x]), on1 = __ldg(&g_onorm[p.y]);
        float on2 = __ldg(&g_onorm[p.z]), on3 = __ldg(&g_onorm[p.w]);
        uint2 u0 = __ldg((const uint2*)&Y[p.x * 64 + pbase]);
        uint2 u1 = __ldg((const uint2*)&Y[p.y * 64 + pbase]);
        uint2 u2 = __ldg((const uint2*)&Y[p.z * 64 + pbase]);
        uint2 u3 = __ldg((const uint2*)&Y[p.w * 64 + pbase]);
        bf2acc_on(a0, u0, on0); bf2acc_on(a1, u1, on1);
        bf2acc_on(a2, u2, on2); bf2acc_on(a3, u3, on3);
    }
    for (; j < e; j++) {
        int s0 = __ldg(&g_perm[j]);
        bf2acc_on(a0, __ldg((const uint2*)&Y[s0 * 64 + pbase]), __ldg(&g_onorm[s0]));
    }

    float in = g_inorm[v];
    float4 bb = __ldg((const float4*)&b[col]);
    float4 r;
    r.x = fmaxf((a0.x + a1.x + a2.x + a3.x) * in + bb.x, 0.f);
    r.y = fmaxf((a0.y + a1.y + a2.y + a3.y) * in + bb.y, 0.f);
    r.z = fmaxf((a0.z + a1.z + a2.z + a3.z) * in + bb.z, 0.f);
    r.w = fmaxf((a0.w + a1.w + a2.w + a3.w) * in + bb.w, 0.f);
    *(float4*)&Hout[v * 128 + col] = r;
}

// ---------------- final: warp per node, float2 lanes, int4 perm loads ----------------
__global__ __launch_bounds__(256) void k_final(const float* __restrict__ bo,
                                               float* __restrict__ Out) {
    int v = (blockIdx.x * 256 + threadIdx.x) >> 5;
    if (v >= NN) return;
    int lane = threadIdx.x & 31;
    int col = lane * 2;
    int s = g_rs[v], e = g_rs[v + 1];
    float2 a0 = make_float2(0.f, 0.f), a1 = a0, a2 = a0, a3 = a0;
    int j = s;
    for (; j < e && (j & 3); j++) {
        float2 v0 = __ldg((const float2*)&g_z[__ldg(&g_perm[j]) * 64 + col]);
        a0.x += v0.x; a0.y += v0.y;
    }
    for (; j + 4 <= e; j += 4) {
        int4 p = *(const int4*)&g_perm[j];
        float2 v0 = __ldg((const float2*)&g_z[p.x * 64 + col]);
        float2 v1 = __ldg((const float2*)&g_z[p.y * 64 + col]);
        float2 v2 = __ldg((const float2*)&g_z[p.z * 64 + col]);
        float2 v3 = __ldg((const float2*)&g_z[p.w * 64 + col]);
        a0.x += v0.x; a0.y += v0.y;
        a1.x += v1.x; a1.y += v1.y;
        a2.x += v2.x; a2.y += v2.y;
        a3.x += v3.x; a3.y += v3.y;
    }
    for (; j < e; j++) {
        float2 v0 = __ldg((const float2*)&g_z[__ldg(&g_perm[j]) * 64 + col]);
        a0.x += v0.x; a0.y += v0.y;
    }
    float2 bb = __ldg((const float2*)&bo[col]);
    Out[v * 64 + col + 0] = (a0.x + a1.x) + (a2.x + a3.x) + bb.x;
    Out[v * 64 + col + 1] = (a0.y + a1.y) + (a2.y + a3.y) + bb.y;
}

// ---------------- host ----------------
extern "C" void kernel_launch(void* const* d_in, const int* in_sizes, int n_in,
                              void* d_out, int out_size) {
    const float* feats = (const float*)d_in[0];
    const int*   src   = (const int*)d_in[1];
    const int*   dst   = (const int*)d_in[2];
    const float* W0    = (const float*)d_in[3];
    const float* b0    = (const float*)d_in[4];
    const float* W1    = (const float*)d_in[5];
    const float* b1    = (const float*)d_in[6];
    const float* W2    = (const float*)d_in[7];
    const float* b2    = (const float*)d_in[8];
    const float* Wo    = (const float*)d_in[9];
    const float* bo    = (const float*)d_in[10];
    float* out = (float*)d_out;

    void *p_deg, *p_h, *p_y, *p_z;
    cudaGetSymbolAddress(&p_deg, g_deg);
    cudaGetSymbolAddress(&p_h, g_h);
    cudaGetSymbolAddress(&p_y, g_y);
    cudaGetSymbolAddress(&p_z, g_z);
    float* hbuf = (float*)p_h;
    __nv_bfloat162* ybuf = (__nv_bfloat162*)p_y;
    float* zbuf = (float*)p_z;

    cudaMemsetAsync(p_deg, 0, 2 * NN * sizeof(int));   // single memset (launch #1)

    dim3 gconv((NN + 63) / 64, 2);
    int gz = (NN + 63) / 64;
    int ab = (NN * 32 + 255) / 256;
    int eb = (NE + 255) / 256;

    k_fused1<<<GB1 + DEGB, 256>>>(src, dst, feats, W0, ybuf);   // #2: gemm1(unscaled) + degree
    k_scan<<<1, 1024>>>();                                       // #3
    k_build<<<eb, 256>>>(src, dst);                              // #4
    k_agg_on<<<ab, 256>>>(ybuf, b0, hbuf);                       // #5
    k_gemm_conv_tc<<<gconv, 256>>>(hbuf, W1, ybuf);              // #6  <- ncu window
    k_agg<<<ab, 256>>>(ybuf, b1, hbuf + (long long)NN * 128);
    k_gemm_conv_tc<<<gconv, 256>>>(hbuf + 1ll * NN * 128, W2, ybuf);
    k_agg<<<ab, 256>>>(ybuf, b2, hbuf + 2ll * NN * 128);
    k_gemm_z_tc<<<gz, 256>>>(hbuf, Wo, zbuf);
    k_final<<<ab, 256>>>(bo, out);
}

// round 13
// speedup vs baseline: 1.0262x; 1.0262x over previous
#include <cuda_runtime.h>
#include <cuda_bf16.h>
#include <cstdint>

#define NN 100000
#define NE 1600000
#define FH 128
#define CC 64
#define GB1 3126          // gemm blocks in fused kernel: ceil(NN/64)*2
#define DEGB 6250         // degree blocks: ceil(NE/256)

// ---------------- scratch ----------------
__device__ float g_h[3ll * NN * FH];                 // h1,h2,h3 (fp32)
__device__ __nv_bfloat162 g_y[(long long)NN * 64];   // Y packed bf16x2
__device__ float g_z[(long long)NN * CC];
__device__ __align__(16) float g_onorm[NN];
__device__ __align__(16) float g_inorm[NN];
__device__ __align__(16) int   g_deg[2 * NN];        // [0,NN)=indeg, [NN,2NN)=outdeg
__device__ __align__(16) int   g_rs[NN + 4];
__device__ __align__(16) int   g_cur[NN + 4];
__device__ __align__(16) int   g_perm[NE];

// ---------------- helpers ----------------
__device__ __forceinline__ uint32_t to_tf32(float x) {
    uint32_t y;
    asm("cvt.rna.tf32.f32 %0, %1;" : "=r"(y) : "f"(x));
    return y;
}
__device__ __forceinline__ float to_tf32f(float x) {
    return __uint_as_float(to_tf32(x));
}

__device__ __forceinline__ void mma_tf32(float* c, const uint32_t* a, uint32_t b0, uint32_t b1) {
    asm volatile(
        "mma.sync.aligned.m16n8k8.row.col.f32.tf32.tf32.f32 "
        "{%0,%1,%2,%3}, {%4,%5,%6,%7}, {%8,%9}, {%0,%1,%2,%3};"
        : "+f"(c[0]), "+f"(c[1]), "+f"(c[2]), "+f"(c[3])
        : "r"(a[0]), "r"(a[1]), "r"(a[2]), "r"(a[3]), "r"(b0), "r"(b1));
}

// ---------------- TF32 conv GEMM body ----------------
template <bool SCALE>
__device__ __forceinline__ void gemm_conv_body(const float* __restrict__ X,
                                               const float* __restrict__ W,
                                               __nv_bfloat162* __restrict__ Y,
                                               int bx, int by) {
    __shared__ float As[64][36];
    __shared__ float Ws[32][72];
    int tid = threadIdx.x;
    int warp = tid >> 5, lane = tid & 31;
    int gid = lane >> 2, tig = lane & 3;
    int m0 = (warp & 3) * 16;
    int ng = warp >> 2;
    int row0 = bx * 64;
    int nh = by * 64;

    float acc[4][4];
#pragma unroll
    for (int i = 0; i < 4; i++)
#pragma unroll
        for (int j = 0; j < 4; j++) acc[i][j] = 0.f;

    float4 pa[2], pw[2];

    auto ldA = [&](int k0) {
#pragma unroll
        for (int u = 0; u < 2; u++) {
            int i = tid + u * 256;
            int m = i >> 3, kq = (i & 7) * 4;
            int r = row0 + m;
            pa[u] = (r < NN) ? *(const float4*)&X[r * 128 + k0 + kq]
                             : make_float4(0.f, 0.f, 0.f, 0.f);
        }
    };
    auto ldW = [&](int k0) {
#pragma unroll
        for (int u = 0; u < 2; u++) {
            int i = tid + u * 256;
            int k = i >> 4, nq = (i & 15) * 4;
            pw[u] = *(const float4*)&W[(k0 + k) * 128 + nh + nq];
        }
    };
    auto stAW = [&]() {
#pragma unroll
        for (int u = 0; u < 2; u++) {
            int i = tid + u * 256;
            int m = i >> 3, kq = (i & 7) * 4;
            As[m][kq + 0] = to_tf32f(pa[u].x);
            As[m][kq + 1] = to_tf32f(pa[u].y);
            As[m][kq + 2] = to_tf32f(pa[u].z);
            As[m][kq + 3] = to_tf32f(pa[u].w);
            int k = i >> 4, nq = (i & 15) * 4;
            Ws[k][nq + 0] = to_tf32f(pw[u].x);
            Ws[k][nq + 1] = to_tf32f(pw[u].y);
            Ws[k][nq + 2] = to_tf32f(pw[u].z);
            Ws[k][nq + 3] = to_tf32f(pw[u].w);
        }
    };

    ldA(0); ldW(0);
    stAW();
    __syncthreads();

    for (int kc = 0; kc < 4; kc++) {
        if (kc < 3) { ldA((kc + 1) * 32); ldW((kc + 1) * 32); }
#pragma unroll
        for (int ks = 0; ks < 4; ks++) {
            int kk = ks * 8;
            uint32_t a[4];
            a[0] = __float_as_uint(As[m0 + gid][kk + tig]);
            a[1] = __float_as_uint(As[m0 + gid + 8][kk + tig]);
            a[2] = __float_as_uint(As[m0 + gid][kk + tig + 4]);
            a[3] = __float_as_uint(As[m0 + gid + 8][kk + tig + 4]);
#pragma unroll
            for (int nt = 0; nt < 4; nt++) {
                uint32_t b0 = __float_as_uint(Ws[kk + tig][ng * 32 + nt * 8 + gid]);
                uint32_t b1 = __float_as_uint(Ws[kk + tig + 4][ng * 32 + nt * 8 + gid]);
                mma_tf32(acc[nt], a, b0, b1);
            }
        }
        __syncthreads();
        if (kc < 3) {
            stAW();
            __syncthreads();
        }
    }

    int r0 = row0 + m0 + gid;
    int r1 = r0 + 8;
    float on0 = 1.f, on1 = 1.f;
    if (SCALE) {
        if (r0 < NN) on0 = __ldg(&g_onorm[r0]);
        if (r1 < NN) on1 = __ldg(&g_onorm[r1]);
    }
#pragma unroll
    for (int nt = 0; nt < 4; nt++) {
        int cp = (nh + ng * 32 + nt * 8 + tig * 2) >> 1;
        if (r0 < NN) Y[r0 * 64 + cp] = __float22bfloat162_rn(make_float2(acc[nt][0] * on0, acc[nt][1] * on0));
        if (r1 < NN) Y[r1 * 64 + cp] = __float22bfloat162_rn(make_float2(acc[nt][2] * on1, acc[nt][3] * on1));
    }
}

// ---------------- fused: layer-1 GEMM (unscaled) + degree counting ----------------
__global__ __launch_bounds__(256) void k_fused1(const int* __restrict__ src,
                                                const int* __restrict__ dst,
                                                const float* __restrict__ X,
                                                const float* __restrict__ W,
                                                __nv_bfloat162* __restrict__ Y) {
    if (blockIdx.x < GB1) {
        gemm_conv_body<false>(X, W, Y, blockIdx.x >> 1, blockIdx.x & 1);
    } else {
        int e = (blockIdx.x - GB1) * 256 + threadIdx.x;
        if (e < NE) {
            atomicAdd(&g_deg[NN + src[e]], 1);
            atomicAdd(&g_deg[dst[e]], 1);
        }
    }
}

__global__ __launch_bounds__(256) void k_gemm_conv_tc(const float* __restrict__ X,
                                                      const float* __restrict__ W,
                                                      __nv_bfloat162* __restrict__ Y) {
    gemm_conv_body<true>(X, W, Y, blockIdx.x, blockIdx.y);
}

// ---------------- scan + norms ----------------
__global__ __launch_bounds__(1024) void k_scan() {
    __shared__ int sums[1024];
    int tid = threadIdx.x;
    const int chunk = 100;
    int b = tid * chunk;
    int s = 0;
    if (b < NN) {
        const int4* p = (const int4*)(g_deg + b);
#pragma unroll 5
        for (int i = 0; i < 25; i++) {
            int4 v = p[i];
            s += v.x + v.y + v.z + v.w;
        }
    }
    sums[tid] = s;
    __syncthreads();
    for (int off = 1; off < 1024; off <<= 1) {
        int v = (tid >= off) ? sums[tid - off] : 0;
        __syncthreads();
        sums[tid] += v;
        __syncthreads();
    }
    int run = (tid == 0) ? 0 : sums[tid - 1];
    if (b < NN) {
        const int4* pi = (const int4*)(g_deg + b);
        const int4* po = (const int4*)(g_deg + NN + b);
        for (int i = 0; i < 25; i++) {
            int4 di = pi[i];
            int4 dq = po[i];
            int4 r4;
            r4.x = run; run += di.x;
            r4.y = run; run += di.y;
            r4.z = run; run += di.z;
            r4.w = run; run += di.w;
            *(int4*)(g_rs + b + i * 4) = r4;
            *(int4*)(g_cur + b + i * 4) = r4;
            float4 in4, on4;
            in4.x = di.x > 0 ? rsqrtf((float)di.x) : 0.f;
            in4.y = di.y > 0 ? rsqrtf((float)di.y) : 0.f;
            in4.z = di.z > 0 ? rsqrtf((float)di.z) : 0.f;
            in4.w = di.w > 0 ? rsqrtf((float)di.w) : 0.f;
            on4.x = dq.x > 0 ? rsqrtf((float)dq.x) : 0.f;
            on4.y = dq.y > 0 ? rsqrtf((float)dq.y) : 0.f;
            on4.z = dq.z > 0 ? rsqrtf((float)dq.z) : 0.f;
            on4.w = dq.w > 0 ? rsqrtf((float)dq.w) : 0.f;
            *(float4*)(g_inorm + b + i * 4) = in4;
            *(float4*)(g_onorm + b + i * 4) = on4;
        }
        if (b + chunk == NN) g_rs[NN] = run;
    }
}

__global__ void k_build(const int* __restrict__ src, const int* __restrict__ dst) {
    int e = blockIdx.x * blockDim.x + threadIdx.x;
    if (e < NE) {
        int p = atomicAdd(&g_cur[dst[e]], 1);
        g_perm[p] = src[e];
    }
}

// ---------------- TF32 GEMM: Z[N,64] = concat(h1,h2,h3) @ Wo[384,64] ----------------
__global__ __launch_bounds__(256) void k_gemm_z_tc(const float* __restrict__ Hc,
                                                   const float* __restrict__ Wo,
                                                   float* __restrict__ Z) {
    __shared__ float As[64][36];
    __shared__ float Ws[32][72];
    int tid = threadIdx.x;
    int warp = tid >> 5, lane = tid & 31;
    int gid = lane >> 2, tig = lane & 3;
    int m0 = (warp & 3) * 16;
    int ng = warp >> 2;
    int row0 = blockIdx.x * 64;

    float acc[4][4];
#pragma unroll
    for (int i = 0; i < 4; i++)
#pragma unroll
        for (int j = 0; j < 4; j++) acc[i][j] = 0.f;

    float4 pa[2], pw[2];

    auto ldA = [&](int kc) {
        int k0 = kc * 32;
        const float* Xb = Hc + (long long)(k0 >> 7) * NN * 128;
        int cb = k0 & 127;
#pragma unroll
        for (int u = 0; u < 2; u++) {
            int i = tid + u * 256;
            int m = i >> 3, kq = (i & 7) * 4;
            int r = row0 + m;
            pa[u] = (r < NN) ? *(const float4*)&Xb[r * 128 + cb + kq]
                             : make_float4(0.f, 0.f, 0.f, 0.f);
        }
    };
    auto ldW = [&](int kc) {
        int k0 = kc * 32;
#pragma unroll
        for (int u = 0; u < 2; u++) {
            int i = tid + u * 256;
            int k = i >> 4, nq = (i & 15) * 4;
            pw[u] = *(const float4*)&Wo[(k0 + k) * 64 + nq];
        }
    };
    auto stAW = [&]() {
#pragma unroll
        for (int u = 0; u < 2; u++) {
            int i = tid + u * 256;
            int m = i >> 3, kq = (i & 7) * 4;
            As[m][kq + 0] = to_tf32f(pa[u].x);
            As[m][kq + 1] = to_tf32f(pa[u].y);
            As[m][kq + 2] = to_tf32f(pa[u].z);
            As[m][kq + 3] = to_tf32f(pa[u].w);
            int k = i >> 4, nq = (i & 15) * 4;
            Ws[k][nq + 0] = to_tf32f(pw[u].x);
            Ws[k][nq + 1] = to_tf32f(pw[u].y);
            Ws[k][nq + 2] = to_tf32f(pw[u].z);
            Ws[k][nq + 3] = to_tf32f(pw[u].w);
        }
    };

    ldA(0); ldW(0);
    stAW();
    __syncthreads();

    for (int kc = 0; kc < 12; kc++) {
        if (kc < 11) { ldA(kc + 1); ldW(kc + 1); }
#pragma unroll
        for (int ks = 0; ks < 4; ks++) {
            int kk = ks * 8;
            uint32_t a[4];
            a[0] = __float_as_uint(As[m0 + gid][kk + tig]);
            a[1] = __float_as_uint(As[m0 + gid + 8][kk + tig]);
            a[2] = __float_as_uint(As[m0 + gid][kk + tig + 4]);
            a[3] = __float_as_uint(As[m0 + gid + 8][kk + tig + 4]);
#pragma unroll
            for (int nt = 0; nt < 4; nt++) {
                uint32_t b0 = __float_as_uint(Ws[kk + tig][ng * 32 + nt * 8 + gid]);
                uint32_t b1 = __float_as_uint(Ws[kk + tig + 4][ng * 32 + nt * 8 + gid]);
                mma_tf32(acc[nt], a, b0, b1);
            }
        }
        __syncthreads();
        if (kc < 11) {
            stAW();
            __syncthreads();
        }
    }

    int r0 = row0 + m0 + gid;
    int r1 = r0 + 8;
#pragma unroll
    for (int nt = 0; nt < 4; nt++) {
        int c = ng * 32 + nt * 8 + tig * 2;
        if (r0 < NN) *(float2*)&Z[r0 * 64 + c] = make_float2(acc[nt][0], acc[nt][1]);
        if (r1 < NN) *(float2*)&Z[r1 * 64 + c] = make_float2(acc[nt][2], acc[nt][3]);
    }
}

// ---------------- aggregation helpers ----------------
__device__ __forceinline__ void bf2acc(float4& a, uint2 u) {
    __nv_bfloat162 p0 = *(__nv_bfloat162*)&u.x;
    __nv_bfloat162 p1 = *(__nv_bfloat162*)&u.y;
    float2 f0 = __bfloat1622float2(p0);
    float2 f1 = __bfloat1622float2(p1);
    a.x += f0.x; a.y += f0.y; a.z += f1.x; a.w += f1.y;
}
__device__ __forceinline__ void bf2acc_on(float4& a, uint2 u, float on) {
    __nv_bfloat162 p0 = *(__nv_bfloat162*)&u.x;
    __nv_bfloat162 p1 = *(__nv_bfloat162*)&u.y;
    float2 f0 = __bfloat1622float2(p0);
    float2 f1 = __bfloat1622float2(p1);
    a.x += on * f0.x; a.y += on * f0.y; a.z += on * f1.x; a.w += on * f1.y;
}

// ---------------- agg (layers 2,3): MLP=8 gather ----------------
__global__ __launch_bounds__(256) void k_agg(const __nv_bfloat162* __restrict__ Y,
                                             const float* __restrict__ b,
                                             float* __restrict__ Hout) {
    int v = (blockIdx.x * 256 + threadIdx.x) >> 5;
    if (v >= NN) return;
    int lane = threadIdx.x & 31;
    int col = lane * 4;
    int pbase = lane * 2;
    int s = g_rs[v], e = g_rs[v + 1];
    float4 a0 = make_float4(0.f, 0.f, 0.f, 0.f), a1 = a0, a2 = a0, a3 = a0;

    int j = s;
    for (; j + 8 <= e; j += 8) {
        int s0 = __ldg(&g_perm[j + 0]), s1 = __ldg(&g_perm[j + 1]);
        int s2 = __ldg(&g_perm[j + 2]), s3 = __ldg(&g_perm[j + 3]);
        int s4 = __ldg(&g_perm[j + 4]), s5 = __ldg(&g_perm[j + 5]);
        int s6 = __ldg(&g_perm[j + 6]), s7 = __ldg(&g_perm[j + 7]);
        uint2 u0 = __ldg((const uint2*)&Y[s0 * 64 + pbase]);
        uint2 u1 = __ldg((const uint2*)&Y[s1 * 64 + pbase]);
        uint2 u2 = __ldg((const uint2*)&Y[s2 * 64 + pbase]);
        uint2 u3 = __ldg((const uint2*)&Y[s3 * 64 + pbase]);
        uint2 u4 = __ldg((const uint2*)&Y[s4 * 64 + pbase]);
        uint2 u5 = __ldg((const uint2*)&Y[s5 * 64 + pbase]);
        uint2 u6 = __ldg((const uint2*)&Y[s6 * 64 + pbase]);
        uint2 u7 = __ldg((const uint2*)&Y[s7 * 64 + pbase]);
        bf2acc(a0, u0); bf2acc(a1, u1); bf2acc(a2, u2); bf2acc(a3, u3);
        bf2acc(a0, u4); bf2acc(a1, u5); bf2acc(a2, u6); bf2acc(a3, u7);
    }
    if (j + 4 <= e) {
        int s0 = __ldg(&g_perm[j + 0]), s1 = __ldg(&g_perm[j + 1]);
        int s2 = __ldg(&g_perm[j + 2]), s3 = __ldg(&g_perm[j + 3]);
        uint2 u0 = __ldg((const uint2*)&Y[s0 * 64 + pbase]);
        uint2 u1 = __ldg((const uint2*)&Y[s1 * 64 + pbase]);
        uint2 u2 = __ldg((const uint2*)&Y[s2 * 64 + pbase]);
        uint2 u3 = __ldg((const uint2*)&Y[s3 * 64 + pbase]);
        bf2acc(a0, u0); bf2acc(a1, u1); bf2acc(a2, u2); bf2acc(a3, u3);
        j += 4;
    }
    for (; j < e; j++)
        bf2acc(a0, __ldg((const uint2*)&Y[__ldg(&g_perm[j]) * 64 + pbase]));

    float in = g_inorm[v];
    float4 bb = __ldg((const float4*)&b[col]);
    float4 r;
    r.x = fmaxf((a0.x + a1.x + a2.x + a3.x) * in + bb.x, 0.f);
    r.y = fmaxf((a0.y + a1.y + a2.y + a3.y) * in + bb.y, 0.f);
    r.z = fmaxf((a0.z + a1.z + a2.z + a3.z) * in + bb.z, 0.f);
    r.w = fmaxf((a0.w + a1.w + a2.w + a3.w) * in + bb.w, 0.f);
    *(float4*)&Hout[v * 128 + col] = r;
}

// ---------------- agg (layer 1): per-edge onorm, MLP=8 ----------------
__global__ __launch_bounds__(256) void k_agg_on(const __nv_bfloat162* __restrict__ Y,
                                                const float* __restrict__ b,
                                                float* __restrict__ Hout) {
    int v = (blockIdx.x * 256 + threadIdx.x) >> 5;
    if (v >= NN) return;
    int lane = threadIdx.x & 31;
    int col = lane * 4;
    int pbase = lane * 2;
    int s = g_rs[v], e = g_rs[v + 1];
    float4 a0 = make_float4(0.f, 0.f, 0.f, 0.f), a1 = a0, a2 = a0, a3 = a0;

    int j = s;
    for (; j + 8 <= e; j += 8) {
        int s0 = __ldg(&g_perm[j + 0]), s1 = __ldg(&g_perm[j + 1]);
        int s2 = __ldg(&g_perm[j + 2]), s3 = __ldg(&g_perm[j + 3]);
        int s4 = __ldg(&g_perm[j + 4]), s5 = __ldg(&g_perm[j + 5]);
        int s6 = __ldg(&g_perm[j + 6]), s7 = __ldg(&g_perm[j + 7]);
        float on0 = __ldg(&g_onorm[s0]), on1 = __ldg(&g_onorm[s1]);
        float on2 = __ldg(&g_onorm[s2]), on3 = __ldg(&g_onorm[s3]);
        float on4 = __ldg(&g_onorm[s4]), on5 = __ldg(&g_onorm[s5]);
        float on6 = __ldg(&g_onorm[s6]), on7 = __ldg(&g_onorm[s7]);
        uint2 u0 = __ldg((const uint2*)&Y[s0 * 64 + pbase]);
        uint2 u1 = __ldg((const uint2*)&Y[s1 * 64 + pbase]);
        uint2 u2 = __ldg((const uint2*)&Y[s2 * 64 + pbase]);
        uint2 u3 = __ldg((const uint2*)&Y[s3 * 64 + pbase]);
        uint2 u4 = __ldg((const uint2*)&Y[s4 * 64 + pbase]);
        uint2 u5 = __ldg((const uint2*)&Y[s5 * 64 + pbase]);
        uint2 u6 = __ldg((const uint2*)&Y[s6 * 64 + pbase]);
        uint2 u7 = __ldg((const uint2*)&Y[s7 * 64 + pbase]);
        bf2acc_on(a0, u0, on0); bf2acc_on(a1, u1, on1);
        bf2acc_on(a2, u2, on2); bf2acc_on(a3, u3, on3);
        bf2acc_on(a0, u4, on4); bf2acc_on(a1, u5, on5);
        bf2acc_on(a2, u6, on6); bf2acc_on(a3, u7, on7);
    }
    if (j + 4 <= e) {
        int s0 = __ldg(&g_perm[j + 0]), s1 = __ldg(&g_perm[j + 1]);
        int s2 = __ldg(&g_perm[j + 2]), s3 = __ldg(&g_perm[j + 3]);
        float on0 = __ldg(&g_onorm[s0]), on1 = __ldg(&g_onorm[s1]);
        float on2 = __ldg(&g_onorm[s2]), on3 = __ldg(&g_onorm[s3]);
        uint2 u0 = __ldg((const uint2*)&Y[s0 * 64 + pbase]);
        uint2 u1 = __ldg((const uint2*)&Y[s1 * 64 + pbase]);
        uint2 u2 = __ldg((const uint2*)&Y[s2 * 64 + pbase]);
        uint2 u3 = __ldg((const uint2*)&Y[s3 * 64 + pbase]);
        bf2acc_on(a0, u0, on0); bf2acc_on(a1, u1, on1);
        bf2acc_on(a2, u2, on2); bf2acc_on(a3, u3, on3);
        j += 4;
    }
    for (; j < e; j++) {
        int s0 = __ldg(&g_perm[j]);
        bf2acc_on(a0, __ldg((const uint2*)&Y[s0 * 64 + pbase]), __ldg(&g_onorm[s0]));
    }

    float in = g_inorm[v];
    float4 bb = __ldg((const float4*)&b[col]);
    float4 r;
    r.x = fmaxf((a0.x + a1.x + a2.x + a3.x) * in + bb.x, 0.f);
    r.y = fmaxf((a0.y + a1.y + a2.y + a3.y) * in + bb.y, 0.f);
    r.z = fmaxf((a0.z + a1.z + a2.z + a3.z) * in + bb.z, 0.f);
    r.w = fmaxf((a0.w + a1.w + a2.w + a3.w) * in + bb.w, 0.f);
    *(float4*)&Hout[v * 128 + col] = r;
}

// ---------------- final: warp per node, MLP=8 ----------------
__global__ __launch_bounds__(256) void k_final(const float* __restrict__ bo,
                                               float* __restrict__ Out) {
    int v = (blockIdx.x * 256 + threadIdx.x) >> 5;
    if (v >= NN) return;
    int lane = threadIdx.x & 31;
    int col = lane * 2;
    int s = g_rs[v], e = g_rs[v + 1];
    float2 a0 = make_float2(0.f, 0.f), a1 = a0, a2 = a0, a3 = a0;
    int j = s;
    for (; j + 8 <= e; j += 8) {
        int s0 = __ldg(&g_perm[j + 0]), s1 = __ldg(&g_perm[j + 1]);
        int s2 = __ldg(&g_perm[j + 2]), s3 = __ldg(&g_perm[j + 3]);
        int s4 = __ldg(&g_perm[j + 4]), s5 = __ldg(&g_perm[j + 5]);
        int s6 = __ldg(&g_perm[j + 6]), s7 = __ldg(&g_perm[j + 7]);
        float2 v0 = __ldg((const float2*)&g_z[s0 * 64 + col]);
        float2 v1 = __ldg((const float2*)&g_z[s1 * 64 + col]);
        float2 v2 = __ldg((const float2*)&g_z[s2 * 64 + col]);
        float2 v3 = __ldg((const float2*)&g_z[s3 * 64 + col]);
        float2 v4 = __ldg((const float2*)&g_z[s4 * 64 + col]);
        float2 v5 = __ldg((const float2*)&g_z[s5 * 64 + col]);
        float2 v6 = __ldg((const float2*)&g_z[s6 * 64 + col]);
        float2 v7 = __ldg((const float2*)&g_z[s7 * 64 + col]);
        a0.x += v0.x + v4.x; a0.y += v0.y + v4.y;
        a1.x += v1.x + v5.x; a1.y += v1.y + v5.y;
        a2.x += v2.x + v6.x; a2.y += v2.y + v6.y;
        a3.x += v3.x + v7.x; a3.y += v3.y + v7.y;
    }
    if (j + 4 <= e) {
        int s0 = __ldg(&g_perm[j + 0]), s1 = __ldg(&g_perm[j + 1]);
        int s2 = __ldg(&g_perm[j + 2]), s3 = __ldg(&g_perm[j + 3]);
        float2 v0 = __ldg((const float2*)&g_z[s0 * 64 + col]);
        float2 v1 = __ldg((const float2*)&g_z[s1 * 64 + col]);
        float2 v2 = __ldg((const float2*)&g_z[s2 * 64 + col]);
        float2 v3 = __ldg((const float2*)&g_z[s3 * 64 + col]);
        a0.x += v0.x; a0.y += v0.y;
        a1.x += v1.x; a1.y += v1.y;
        a2.x += v2.x; a2.y += v2.y;
        a3.x += v3.x; a3.y += v3.y;
        j += 4;
    }
    for (; j < e; j++) {
        float2 v0 = __ldg((const float2*)&g_z[__ldg(&g_perm[j]) * 64 + col]);
        a0.x += v0.x; a0.y += v0.y;
    }
    float2 bb = __ldg((const float2*)&bo[col]);
    Out[v * 64 + col + 0] = (a0.x + a1.x) + (a2.x + a3.x) + bb.x;
    Out[v * 64 + col + 1] = (a0.y + a1.y) + (a2.y + a3.y) + bb.y;
}

// ---------------- host ----------------
extern "C" void kernel_launch(void* const* d_in, const int* in_sizes, int n_in,
                              void* d_out, int out_size) {
    const float* feats = (const float*)d_in[0];
    const int*   src   = (const int*)d_in[1];
    const int*   dst   = (const int*)d_in[2];
    const float* W0    = (const float*)d_in[3];
    const float* b0    = (const float*)d_in[4];
    const float* W1    = (const float*)d_in[5];
    const float* b1    = (const float*)d_in[6];
    const float* W2    = (const float*)d_in[7];
    const float* b2    = (const float*)d_in[8];
    const float* Wo    = (const float*)d_in[9];
    const float* bo    = (const float*)d_in[10];
    float* out = (float*)d_out;

    void *p_deg, *p_h, *p_y, *p_z;
    cudaGetSymbolAddress(&p_deg, g_deg);
    cudaGetSymbolAddress(&p_h, g_h);
    cudaGetSymbolAddress(&p_y, g_y);
    cudaGetSymbolAddress(&p_z, g_z);
    float* hbuf = (float*)p_h;
    __nv_bfloat162* ybuf = (__nv_bfloat162*)p_y;
    float* zbuf = (float*)p_z;

    cudaMemsetAsync(p_deg, 0, 2 * NN * sizeof(int));

    dim3 gconv((NN + 63) / 64, 2);
    int gz = (NN + 63) / 64;
    int ab = (NN * 32 + 255) / 256;
    int eb = (NE + 255) / 256;

    k_fused1<<<GB1 + DEGB, 256>>>(src, dst, feats, W0, ybuf);   // #2
    k_scan<<<1, 1024>>>();                                       // #3
    k_build<<<eb, 256>>>(src, dst);                              // #4
    k_agg_on<<<ab, 256>>>(ybuf, b0, hbuf);                       // #5
    k_gemm_conv_tc<<<gconv, 256>>>(hbuf, W1, ybuf);              // #6  <- ncu window
    k_agg<<<ab, 256>>>(ybuf, b1, hbuf + (long long)NN * 128);
    k_gemm_conv_tc<<<gconv, 256>>>(hbuf + 1ll * NN * 128, W2, ybuf);
    k_agg<<<ab, 256>>>(ybuf, b2, hbuf + 2ll * NN * 128);
    k_gemm_z_tc<<<gz, 256>>>(hbuf, Wo, zbuf);
    k_final<<<ab, 256>>>(bo, out);
}

// round 14
// speedup vs baseline: 1.0536x; 1.0267x over previous
#include <cuda_runtime.h>
#include <cuda_bf16.h>
#include <cstdint>

#define NN 100000
#define NE 1600000
#define FH 128
#define CC 64

// ---------------- scratch ----------------
__device__ float g_h[3ll * NN * FH];                 // h1,h2,h3 (fp32)
__device__ __nv_bfloat162 g_y[(long long)NN * 64];   // Y packed bf16x2 (pre-scaled by onorm)
__device__ float g_z[(long long)NN * CC];
__device__ __align__(16) float g_onorm[NN];
__device__ __align__(16) float g_inorm[NN];
__device__ __align__(16) int   g_deg[2 * NN];        // [0,NN)=indeg, [NN,2NN)=outdeg
__device__ __align__(16) int   g_rs[NN + 4];
__device__ __align__(16) int   g_cur[NN + 4];
__device__ __align__(16) int   g_perm[NE];

// ---------------- helpers ----------------
__device__ __forceinline__ uint32_t to_tf32(float x) {
    uint32_t y;
    asm("cvt.rna.tf32.f32 %0, %1;" : "=r"(y) : "f"(x));
    return y;
}
__device__ __forceinline__ float to_tf32f(float x) {
    return __uint_as_float(to_tf32(x));
}

__device__ __forceinline__ void mma_tf32(float* c, const uint32_t* a, uint32_t b0, uint32_t b1) {
    asm volatile(
        "mma.sync.aligned.m16n8k8.row.col.f32.tf32.tf32.f32 "
        "{%0,%1,%2,%3}, {%4,%5,%6,%7}, {%8,%9}, {%0,%1,%2,%3};"
        : "+f"(c[0]), "+f"(c[1]), "+f"(c[2]), "+f"(c[3])
        : "r"(a[0]), "r"(a[1]), "r"(a[2]), "r"(a[3]), "r"(b0), "r"(b1));
}

// ---------------- graph prep ----------------
__global__ void k_degree(const int* __restrict__ src, const int* __restrict__ dst) {
    int e = blockIdx.x * blockDim.x + threadIdx.x;
    if (e < NE) {
        atomicAdd(&g_deg[NN + src[e]], 1);   // outdeg
        atomicAdd(&g_deg[dst[e]], 1);        // indeg
    }
}

// exclusive scan of indeg -> rs/cur + both norms, int4-vectorized
__global__ __launch_bounds__(1024) void k_scan() {
    __shared__ int sums[1024];
    int tid = threadIdx.x;
    const int chunk = 100;
    int b = tid * chunk;
    int s = 0;
    if (b < NN) {
        const int4* p = (const int4*)(g_deg + b);
#pragma unroll 5
        for (int i = 0; i < 25; i++) {
            int4 v = p[i];
            s += v.x + v.y + v.z + v.w;
        }
    }
    sums[tid] = s;
    __syncthreads();
    for (int off = 1; off < 1024; off <<= 1) {
        int v = (tid >= off) ? sums[tid - off] : 0;
        __syncthreads();
        sums[tid] += v;
        __syncthreads();
    }
    int run = (tid == 0) ? 0 : sums[tid - 1];
    if (b < NN) {
        const int4* pi = (const int4*)(g_deg + b);
        const int4* po = (const int4*)(g_deg + NN + b);
        for (int i = 0; i < 25; i++) {
            int4 di = pi[i];
            int4 dq = po[i];
            int4 r4;
            r4.x = run; run += di.x;
            r4.y = run; run += di.y;
            r4.z = run; run += di.z;
            r4.w = run; run += di.w;
            *(int4*)(g_rs + b + i * 4) = r4;
            *(int4*)(g_cur + b + i * 4) = r4;
            float4 in4, on4;
            in4.x = di.x > 0 ? rsqrtf((float)di.x) : 0.f;
            in4.y = di.y > 0 ? rsqrtf((float)di.y) : 0.f;
            in4.z = di.z > 0 ? rsqrtf((float)di.z) : 0.f;
            in4.w = di.w > 0 ? rsqrtf((float)di.w) : 0.f;
            on4.x = dq.x > 0 ? rsqrtf((float)dq.x) : 0.f;
            on4.y = dq.y > 0 ? rsqrtf((float)dq.y) : 0.f;
            on4.z = dq.z > 0 ? rsqrtf((float)dq.z) : 0.f;
            on4.w = dq.w > 0 ? rsqrtf((float)dq.w) : 0.f;
            *(float4*)(g_inorm + b + i * 4) = in4;
            *(float4*)(g_onorm + b + i * 4) = on4;
        }
        if (b + chunk == NN) g_rs[NN] = run;
    }
}

__global__ void k_build(const int* __restrict__ src, const int* __restrict__ dst) {
    int e = blockIdx.x * blockDim.x + threadIdx.x;
    if (e < NE) {
        int p = atomicAdd(&g_cur[dst[e]], 1);
        g_perm[p] = src[e];
    }
}

// ---------------- TF32 conv GEMM: Y[N,128] = (X @ W) .* onorm (epilogue scale) ----------------
// M=64 x N=64 tile (blockIdx.y = N-half). 256 thr / 8 warps. Register-prefetch pipeline.
__global__ __launch_bounds__(256) void k_gemm_conv_tc(const float* __restrict__ X,
                                                      const float* __restrict__ W,
                                                      __nv_bfloat162* __restrict__ Y) {
    __shared__ float As[64][36];
    __shared__ float Ws[32][72];
    int tid = threadIdx.x;
    int warp = tid >> 5, lane = tid & 31;
    int gid = lane >> 2, tig = lane & 3;
    int m0 = (warp & 3) * 16;
    int ng = warp >> 2;
    int row0 = blockIdx.x * 64;
    int nh = blockIdx.y * 64;

    float acc[4][4];
#pragma unroll
    for (int i = 0; i < 4; i++)
#pragma unroll
        for (int j = 0; j < 4; j++) acc[i][j] = 0.f;

    float4 pa[2], pw[2];

    auto ldA = [&](int k0) {
#pragma unroll
        for (int u = 0; u < 2; u++) {
            int i = tid + u * 256;
            int m = i >> 3, kq = (i & 7) * 4;
            int r = row0 + m;
            pa[u] = (r < NN) ? *(const float4*)&X[r * 128 + k0 + kq]
                             : make_float4(0.f, 0.f, 0.f, 0.f);
        }
    };
    auto ldW = [&](int k0) {
#pragma unroll
        for (int u = 0; u < 2; u++) {
            int i = tid + u * 256;
            int k = i >> 4, nq = (i & 15) * 4;
            pw[u] = *(const float4*)&W[(k0 + k) * 128 + nh + nq];
        }
    };
    auto stAW = [&]() {
#pragma unroll
        for (int u = 0; u < 2; u++) {
            int i = tid + u * 256;
            int m = i >> 3, kq = (i & 7) * 4;
            As[m][kq + 0] = to_tf32f(pa[u].x);
            As[m][kq + 1] = to_tf32f(pa[u].y);
            As[m][kq + 2] = to_tf32f(pa[u].z);
            As[m][kq + 3] = to_tf32f(pa[u].w);
            int k = i >> 4, nq = (i & 15) * 4;
            Ws[k][nq + 0] = to_tf32f(pw[u].x);
            Ws[k][nq + 1] = to_tf32f(pw[u].y);
            Ws[k][nq + 2] = to_tf32f(pw[u].z);
            Ws[k][nq + 3] = to_tf32f(pw[u].w);
        }
    };

    ldA(0); ldW(0);
    stAW();
    __syncthreads();

    for (int kc = 0; kc < 4; kc++) {
        if (kc < 3) { ldA((kc + 1) * 32); ldW((kc + 1) * 32); }
#pragma unroll
        for (int ks = 0; ks < 4; ks++) {
            int kk = ks * 8;
            uint32_t a[4];
            a[0] = __float_as_uint(As[m0 + gid][kk + tig]);
            a[1] = __float_as_uint(As[m0 + gid + 8][kk + tig]);
            a[2] = __float_as_uint(As[m0 + gid][kk + tig + 4]);
            a[3] = __float_as_uint(As[m0 + gid + 8][kk + tig + 4]);
#pragma unroll
            for (int nt = 0; nt < 4; nt++) {
                uint32_t b0 = __float_as_uint(Ws[kk + tig][ng * 32 + nt * 8 + gid]);
                uint32_t b1 = __float_as_uint(Ws[kk + tig + 4][ng * 32 + nt * 8 + gid]);
                mma_tf32(acc[nt], a, b0, b1);
            }
        }
        __syncthreads();
        if (kc < 3) {
            stAW();
            __syncthreads();
        }
    }

    int r0 = row0 + m0 + gid;
    int r1 = r0 + 8;
    float on0 = (r0 < NN) ? __ldg(&g_onorm[r0]) : 0.f;
    float on1 = (r1 < NN) ? __ldg(&g_onorm[r1]) : 0.f;
#pragma unroll
    for (int nt = 0; nt < 4; nt++) {
        int cp = (nh + ng * 32 + nt * 8 + tig * 2) >> 1;
        if (r0 < NN) Y[r0 * 64 + cp] = __float22bfloat162_rn(make_float2(acc[nt][0] * on0, acc[nt][1] * on0));
        if (r1 < NN) Y[r1 * 64 + cp] = __float22bfloat162_rn(make_float2(acc[nt][2] * on1, acc[nt][3] * on1));
    }
}

// ---------------- TF32 GEMM: Z[N,64] = concat(h1,h2,h3) @ Wo[384,64] ----------------
__global__ __launch_bounds__(256) void k_gemm_z_tc(const float* __restrict__ Hc,
                                                   const float* __restrict__ Wo,
                                                   float* __restrict__ Z) {
    __shared__ float As[64][36];
    __shared__ float Ws[32][72];
    int tid = threadIdx.x;
    int warp = tid >> 5, lane = tid & 31;
    int gid = lane >> 2, tig = lane & 3;
    int m0 = (warp & 3) * 16;
    int ng = warp >> 2;
    int row0 = blockIdx.x * 64;

    float acc[4][4];
#pragma unroll
    for (int i = 0; i < 4; i++)
#pragma unroll
        for (int j = 0; j < 4; j++) acc[i][j] = 0.f;

    float4 pa[2], pw[2];

    auto ldA = [&](int kc) {
        int k0 = kc * 32;
        const float* Xb = Hc + (long long)(k0 >> 7) * NN * 128;
        int cb = k0 & 127;
#pragma unroll
        for (int u = 0; u < 2; u++) {
            int i = tid + u * 256;
            int m = i >> 3, kq = (i & 7) * 4;
            int r = row0 + m;
            pa[u] = (r < NN) ? *(const float4*)&Xb[r * 128 + cb + kq]
                             : make_float4(0.f, 0.f, 0.f, 0.f);
        }
    };
    auto ldW = [&](int kc) {
        int k0 = kc * 32;
#pragma unroll
        for (int u = 0; u < 2; u++) {
            int i = tid + u * 256;
            int k = i >> 4, nq = (i & 15) * 4;
            pw[u] = *(const float4*)&Wo[(k0 + k) * 64 + nq];
        }
    };
    auto stAW = [&]() {
#pragma unroll
        for (int u = 0; u < 2; u++) {
            int i = tid + u * 256;
            int m = i >> 3, kq = (i & 7) * 4;
            As[m][kq + 0] = to_tf32f(pa[u].x);
            As[m][kq + 1] = to_tf32f(pa[u].y);
            As[m][kq + 2] = to_tf32f(pa[u].z);
            As[m][kq + 3] = to_tf32f(pa[u].w);
            int k = i >> 4, nq = (i & 15) * 4;
            Ws[k][nq + 0] = to_tf32f(pw[u].x);
            Ws[k][nq + 1] = to_tf32f(pw[u].y);
            Ws[k][nq + 2] = to_tf32f(pw[u].z);
            Ws[k][nq + 3] = to_tf32f(pw[u].w);
        }
    };

    ldA(0); ldW(0);
    stAW();
    __syncthreads();

    for (int kc = 0; kc < 12; kc++) {
        if (kc < 11) { ldA(kc + 1); ldW(kc + 1); }
#pragma unroll
        for (int ks = 0; ks < 4; ks++) {
            int kk = ks * 8;
            uint32_t a[4];
            a[0] = __float_as_uint(As[m0 + gid][kk + tig]);
            a[1] = __float_as_uint(As[m0 + gid + 8][kk + tig]);
            a[2] = __float_as_uint(As[m0 + gid][kk + tig + 4]);
            a[3] = __float_as_uint(As[m0 + gid + 8][kk + tig + 4]);
#pragma unroll
            for (int nt = 0; nt < 4; nt++) {
                uint32_t b0 = __float_as_uint(Ws[kk + tig][ng * 32 + nt * 8 + gid]);
                uint32_t b1 = __float_as_uint(Ws[kk + tig + 4][ng * 32 + nt * 8 + gid]);
                mma_tf32(acc[nt], a, b0, b1);
            }
        }
        __syncthreads();
        if (kc < 11) {
            stAW();
            __syncthreads();
        }
    }

    int r0 = row0 + m0 + gid;
    int r1 = r0 + 8;
#pragma unroll
    for (int nt = 0; nt < 4; nt++) {
        int c = ng * 32 + nt * 8 + tig * 2;
        if (r0 < NN) *(float2*)&Z[r0 * 64 + c] = make_float2(acc[nt][0], acc[nt][1]);
        if (r1 < NN) *(float2*)&Z[r1 * 64 + c] = make_float2(acc[nt][2], acc[nt][3]);
    }
}

// ---------------- aggregation helper ----------------
__device__ __forceinline__ void bf2acc(float4& a, uint2 u) {
    __nv_bfloat162 p0 = *(__nv_bfloat162*)&u.x;
    __nv_bfloat162 p1 = *(__nv_bfloat162*)&u.y;
    float2 f0 = __bfloat1622float2(p0);
    float2 f1 = __bfloat1622float2(p1);
    a.x += f0.x; a.y += f0.y; a.z += f1.x; a.w += f1.y;
}

// ---------------- agg (all layers): Y pre-scaled; MLP=8 gather ----------------
__global__ __launch_bounds__(256) void k_agg(const __nv_bfloat162* __restrict__ Y,
                                             const float* __restrict__ b,
                                             float* __restrict__ Hout) {
    int v = (blockIdx.x * 256 + threadIdx.x) >> 5;
    if (v >= NN) return;
    int lane = threadIdx.x & 31;
    int col = lane * 4;
    int pbase = lane * 2;
    int s = g_rs[v], e = g_rs[v + 1];
    float4 a0 = make_float4(0.f, 0.f, 0.f, 0.f), a1 = a0, a2 = a0, a3 = a0;

    int j = s;
    for (; j + 8 <= e; j += 8) {
        int s0 = __ldg(&g_perm[j + 0]), s1 = __ldg(&g_perm[j + 1]);
        int s2 = __ldg(&g_perm[j + 2]), s3 = __ldg(&g_perm[j + 3]);
        int s4 = __ldg(&g_perm[j + 4]), s5 = __ldg(&g_perm[j + 5]);
        int s6 = __ldg(&g_perm[j + 6]), s7 = __ldg(&g_perm[j + 7]);
        uint2 u0 = __ldg((const uint2*)&Y[s0 * 64 + pbase]);
        uint2 u1 = __ldg((const uint2*)&Y[s1 * 64 + pbase]);
        uint2 u2 = __ldg((const uint2*)&Y[s2 * 64 + pbase]);
        uint2 u3 = __ldg((const uint2*)&Y[s3 * 64 + pbase]);
        uint2 u4 = __ldg((const uint2*)&Y[s4 * 64 + pbase]);
        uint2 u5 = __ldg((const uint2*)&Y[s5 * 64 + pbase]);
        uint2 u6 = __ldg((const uint2*)&Y[s6 * 64 + pbase]);
        uint2 u7 = __ldg((const uint2*)&Y[s7 * 64 + pbase]);
        bf2acc(a0, u0); bf2acc(a1, u1); bf2acc(a2, u2); bf2acc(a3, u3);
        bf2acc(a0, u4); bf2acc(a1, u5); bf2acc(a2, u6); bf2acc(a3, u7);
    }
    if (j + 4 <= e) {
        int s0 = __ldg(&g_perm[j + 0]), s1 = __ldg(&g_perm[j + 1]);
        int s2 = __ldg(&g_perm[j + 2]), s3 = __ldg(&g_perm[j + 3]);
        uint2 u0 = __ldg((const uint2*)&Y[s0 * 64 + pbase]);
        uint2 u1 = __ldg((const uint2*)&Y[s1 * 64 + pbase]);
        uint2 u2 = __ldg((const uint2*)&Y[s2 * 64 + pbase]);
        uint2 u3 = __ldg((const uint2*)&Y[s3 * 64 + pbase]);
        bf2acc(a0, u0); bf2acc(a1, u1); bf2acc(a2, u2); bf2acc(a3, u3);
        j += 4;
    }
    for (; j < e; j++)
        bf2acc(a0, __ldg((const uint2*)&Y[__ldg(&g_perm[j]) * 64 + pbase]));

    float in = g_inorm[v];
    float4 bb = __ldg((const float4*)&b[col]);
    float4 r;
    r.x = fmaxf((a0.x + a1.x + a2.x + a3.x) * in + bb.x, 0.f);
    r.y = fmaxf((a0.y + a1.y + a2.y + a3.y) * in + bb.y, 0.f);
    r.z = fmaxf((a0.z + a1.z + a2.z + a3.z) * in + bb.z, 0.f);
    r.w = fmaxf((a0.w + a1.w + a2.w + a3.w) * in + bb.w, 0.f);
    *(float4*)&Hout[v * 128 + col] = r;
}

// ---------------- final: warp per node, MLP=8 ----------------
__global__ __launch_bounds__(256) void k_final(const float* __restrict__ bo,
                                               float* __restrict__ Out) {
    int v = (blockIdx.x * 256 + threadIdx.x) >> 5;
    if (v >= NN) return;
    int lane = threadIdx.x & 31;
    int col = lane * 2;
    int s = g_rs[v], e = g_rs[v + 1];
    float2 a0 = make_float2(0.f, 0.f), a1 = a0, a2 = a0, a3 = a0;
    int j = s;
    for (; j + 8 <= e; j += 8) {
        int s0 = __ldg(&g_perm[j + 0]), s1 = __ldg(&g_perm[j + 1]);
        int s2 = __ldg(&g_perm[j + 2]), s3 = __ldg(&g_perm[j + 3]);
        int s4 = __ldg(&g_perm[j + 4]), s5 = __ldg(&g_perm[j + 5]);
        int s6 = __ldg(&g_perm[j + 6]), s7 = __ldg(&g_perm[j + 7]);
        float2 v0 = __ldg((const float2*)&g_z[s0 * 64 + col]);
        float2 v1 = __ldg((const float2*)&g_z[s1 * 64 + col]);
        float2 v2 = __ldg((const float2*)&g_z[s2 * 64 + col]);
        float2 v3 = __ldg((const float2*)&g_z[s3 * 64 + col]);
        float2 v4 = __ldg((const float2*)&g_z[s4 * 64 + col]);
        float2 v5 = __ldg((const float2*)&g_z[s5 * 64 + col]);
        float2 v6 = __ldg((const float2*)&g_z[s6 * 64 + col]);
        float2 v7 = __ldg((const float2*)&g_z[s7 * 64 + col]);
        a0.x += v0.x + v4.x; a0.y += v0.y + v4.y;
        a1.x += v1.x + v5.x; a1.y += v1.y + v5.y;
        a2.x += v2.x + v6.x; a2.y += v2.y + v6.y;
        a3.x += v3.x + v7.x; a3.y += v3.y + v7.y;
    }
    if (j + 4 <= e) {
        int s0 = __ldg(&g_perm[j + 0]), s1 = __ldg(&g_perm[j + 1]);
        int s2 = __ldg(&g_perm[j + 2]), s3 = __ldg(&g_perm[j + 3]);
        float2 v0 = __ldg((const float2*)&g_z[s0 * 64 + col]);
        float2 v1 = __ldg((const float2*)&g_z[s1 * 64 + col]);
        float2 v2 = __ldg((const float2*)&g_z[s2 * 64 + col]);
        float2 v3 = __ldg((const float2*)&g_z[s3 * 64 + col]);
        a0.x += v0.x; a0.y += v0.y;
        a1.x += v1.x; a1.y += v1.y;
        a2.x += v2.x; a2.y += v2.y;
        a3.x += v3.x; a3.y += v3.y;
        j += 4;
    }
    for (; j < e; j++) {
        float2 v0 = __ldg((const float2*)&g_z[__ldg(&g_perm[j]) * 64 + col]);
        a0.x += v0.x; a0.y += v0.y;
    }
    float2 bb = __ldg((const float2*)&bo[col]);
    Out[v * 64 + col + 0] = (a0.x + a1.x) + (a2.x + a3.x) + bb.x;
    Out[v * 64 + col + 1] = (a0.y + a1.y) + (a2.y + a3.y) + bb.y;
}

// ---------------- host ----------------
extern "C" void kernel_launch(void* const* d_in, const int* in_sizes, int n_in,
                              void* d_out, int out_size) {
    const float* feats = (const float*)d_in[0];
    const int*   src   = (const int*)d_in[1];
    const int*   dst   = (const int*)d_in[2];
    const float* W0    = (const float*)d_in[3];
    const float* b0    = (const float*)d_in[4];
    const float* W1    = (const float*)d_in[5];
    const float* b1    = (const float*)d_in[6];
    const float* W2    = (const float*)d_in[7];
    const float* b2    = (const float*)d_in[8];
    const float* Wo    = (const float*)d_in[9];
    const float* bo    = (const float*)d_in[10];
    float* out = (float*)d_out;

    void *p_deg, *p_h, *p_y, *p_z;
    cudaGetSymbolAddress(&p_deg, g_deg);
    cudaGetSymbolAddress(&p_h, g_h);
    cudaGetSymbolAddress(&p_y, g_y);
    cudaGetSymbolAddress(&p_z, g_z);
    float* hbuf = (float*)p_h;
    __nv_bfloat162* ybuf = (__nv_bfloat162*)p_y;
    float* zbuf = (float*)p_z;

    cudaMemsetAsync(p_deg, 0, 2 * NN * sizeof(int));

    dim3 gconv((NN + 63) / 64, 2);
    int gz = (NN + 63) / 64;
    int ab = (NN * 32 + 255) / 256;
    int eb = (NE + 255) / 256;

    k_degree<<<eb, 256>>>(src, dst);                          // kernel 1
    k_scan<<<1, 1024>>>();                                    // kernel 2
    k_build<<<eb, 256>>>(src, dst);                           // kernel 3
    k_gemm_conv_tc<<<gconv, 256>>>(feats, W0, ybuf);          // kernel 4  <- ncu window
    k_agg<<<ab, 256>>>(ybuf, b0, hbuf);
    k_gemm_conv_tc<<<gconv, 256>>>(hbuf, W1, ybuf);
    k_agg<<<ab, 256>>>(ybuf, b1, hbuf + (long long)NN * 128);
    k_gemm_conv_tc<<<gconv, 256>>>(hbuf + 1ll * NN * 128, W2, ybuf);
    k_agg<<<ab, 256>>>(ybuf, b2, hbuf + 2ll * NN * 128);
    k_gemm_z_tc<<<gz, 256>>>(hbuf, Wo, zbuf);
    k_final<<<ab, 256>>>(bo, out);
}

// round 16
// speedup vs baseline: 1.0661x; 1.0119x over previous
#include <cuda_runtime.h>
#include <cuda_bf16.h>
#include <cstdint>

#define NN 100000
#define NE 1600000
#define FH 128
#define CC 64

// ---------------- scratch ----------------
__device__ float g_h[3ll * NN * FH];                 // h1,h2,h3 (fp32)
__device__ __nv_bfloat162 g_y[(long long)NN * 64];   // Y packed bf16x2 (pre-scaled by onorm)
__device__ float g_z[(long long)NN * CC];
__device__ __align__(16) float g_onorm[NN];
__device__ __align__(16) float g_inorm[NN];
__device__ __align__(16) int   g_deg[2 * NN];        // [0,NN)=indeg, [NN,2NN)=outdeg
__device__ __align__(16) int   g_rs[NN + 4];
__device__ __align__(16) int   g_cur[NN + 4];
__device__ __align__(16) int   g_perm[NE];

// ---------------- helpers ----------------
__device__ __forceinline__ uint32_t to_tf32(float x) {
    uint32_t y;
    asm("cvt.rna.tf32.f32 %0, %1;" : "=r"(y) : "f"(x));
    return y;
}
__device__ __forceinline__ float to_tf32f(float x) {
    return __uint_as_float(to_tf32(x));
}

__device__ __forceinline__ void mma_tf32(float* c, const uint32_t* a, uint32_t b0, uint32_t b1) {
    asm volatile(
        "mma.sync.aligned.m16n8k8.row.col.f32.tf32.tf32.f32 "
        "{%0,%1,%2,%3}, {%4,%5,%6,%7}, {%8,%9}, {%0,%1,%2,%3};"
        : "+f"(c[0]), "+f"(c[1]), "+f"(c[2]), "+f"(c[3])
        : "r"(a[0]), "r"(a[1]), "r"(a[2]), "r"(a[3]), "r"(b0), "r"(b1));
}

// ---------------- graph prep ----------------
__global__ void k_degree(const int* __restrict__ src, const int* __restrict__ dst) {
    int e = blockIdx.x * blockDim.x + threadIdx.x;
    if (e < NE) {
        atomicAdd(&g_deg[NN + src[e]], 1);   // outdeg
        atomicAdd(&g_deg[dst[e]], 1);        // indeg
    }
}

__global__ __launch_bounds__(1024) void k_scan() {
    __shared__ int sums[1024];
    int tid = threadIdx.x;
    const int chunk = 100;
    int b = tid * chunk;
    int s = 0;
    if (b < NN) {
        const int4* p = (const int4*)(g_deg + b);
#pragma unroll 5
        for (int i = 0; i < 25; i++) {
            int4 v = p[i];
            s += v.x + v.y + v.z + v.w;
        }
    }
    sums[tid] = s;
    __syncthreads();
    for (int off = 1; off < 1024; off <<= 1) {
        int v = (tid >= off) ? sums[tid - off] : 0;
        __syncthreads();
        sums[tid] += v;
        __syncthreads();
    }
    int run = (tid == 0) ? 0 : sums[tid - 1];
    if (b < NN) {
        const int4* pi = (const int4*)(g_deg + b);
        const int4* po = (const int4*)(g_deg + NN + b);
        for (int i = 0; i < 25; i++) {
            int4 di = pi[i];
            int4 dq = po[i];
            int4 r4;
            r4.x = run; run += di.x;
            r4.y = run; run += di.y;
            r4.z = run; run += di.z;
            r4.w = run; run += di.w;
            *(int4*)(g_rs + b + i * 4) = r4;
            *(int4*)(g_cur + b + i * 4) = r4;
            float4 in4, on4;
            in4.x = di.x > 0 ? rsqrtf((float)di.x) : 0.f;
            in4.y = di.y > 0 ? rsqrtf((float)di.y) : 0.f;
            in4.z = di.z > 0 ? rsqrtf((float)di.z) : 0.f;
            in4.w = di.w > 0 ? rsqrtf((float)di.w) : 0.f;
            on4.x = dq.x > 0 ? rsqrtf((float)dq.x) : 0.f;
            on4.y = dq.y > 0 ? rsqrtf((float)dq.y) : 0.f;
            on4.z = dq.z > 0 ? rsqrtf((float)dq.z) : 0.f;
            on4.w = dq.w > 0 ? rsqrtf((float)dq.w) : 0.f;
            *(float4*)(g_inorm + b + i * 4) = in4;
            *(float4*)(g_onorm + b + i * 4) = on4;
        }
        if (b + chunk == NN) g_rs[NN] = run;
    }
}

__global__ void k_build(const int* __restrict__ src, const int* __restrict__ dst) {
    int e = blockIdx.x * blockDim.x + threadIdx.x;
    if (e < NE) {
        int p = atomicAdd(&g_cur[dst[e]], 1);
        g_perm[p] = src[e];
    }
}

// ---------------- TF32 conv GEMM: Y[N,128] = (X @ W) .* onorm ----------------
// Tile M=128 x N=64 (blockIdx.y = N-half). Warp tile M=32 x N=32 (2 m-frags share B frags).
// K-chunks of 16, smem 14.8KB -> 3 blocks/SM. 256 B LDS per mma (vs 384 before).
__global__ __launch_bounds__(256, 3) void k_gemm_conv_tc(const float* __restrict__ X,
                                                         const float* __restrict__ W,
                                                         __nv_bfloat162* __restrict__ Y) {
    __shared__ float As[128][20];   // [m][k] stride 20: banks 4g+t -> conflict-free
    __shared__ float Ws[16][72];    // [k][n] stride 72: banks 8t+g -> conflict-free
    int tid = threadIdx.x;
    int warp = tid >> 5, lane = tid & 31;
    int gid = lane >> 2, tig = lane & 3;
    int m0 = (warp & 3) * 32;       // warp m-offset (2 frags: m0, m0+16)
    int ng = warp >> 2;             // warp n-offset ng*32
    int row0 = blockIdx.x * 128;
    int nh = blockIdx.y * 64;

    float acc[2][4][4];
#pragma unroll
    for (int mf = 0; mf < 2; mf++)
#pragma unroll
        for (int i = 0; i < 4; i++)
#pragma unroll
            for (int j = 0; j < 4; j++) acc[mf][i][j] = 0.f;

    float4 pa[2], pw;

    auto ldA = [&](int k0) {
#pragma unroll
        for (int u = 0; u < 2; u++) {
            int i = tid + u * 256;
            int m = i >> 2, kq = (i & 3) * 4;
            int r = row0 + m;
            pa[u] = (r < NN) ? *(const float4*)&X[r * 128 + k0 + kq]
                             : make_float4(0.f, 0.f, 0.f, 0.f);
        }
    };
    auto ldW = [&](int k0) {
        int k = tid >> 4, nq = (tid & 15) * 4;
        pw = *(const float4*)&W[(k0 + k) * 128 + nh + nq];
    };
    auto stAW = [&]() {
#pragma unroll
        for (int u = 0; u < 2; u++) {
            int i = tid + u * 256;
            int m = i >> 2, kq = (i & 3) * 4;
            As[m][kq + 0] = to_tf32f(pa[u].x);
            As[m][kq + 1] = to_tf32f(pa[u].y);
            As[m][kq + 2] = to_tf32f(pa[u].z);
            As[m][kq + 3] = to_tf32f(pa[u].w);
        }
        int k = tid >> 4, nq = (tid & 15) * 4;
        Ws[k][nq + 0] = to_tf32f(pw.x);
        Ws[k][nq + 1] = to_tf32f(pw.y);
        Ws[k][nq + 2] = to_tf32f(pw.z);
        Ws[k][nq + 3] = to_tf32f(pw.w);
    };

    ldA(0); ldW(0);
    stAW();
    __syncthreads();

    for (int kc = 0; kc < 8; kc++) {
        if (kc < 7) { ldA((kc + 1) * 16); ldW((kc + 1) * 16); }
#pragma unroll
        for (int ks = 0; ks < 2; ks++) {
            int kk = ks * 8;
            uint32_t a[2][4];
#pragma unroll
            for (int mf = 0; mf < 2; mf++) {
                int mr = m0 + mf * 16;
                a[mf][0] = __float_as_uint(As[mr + gid][kk + tig]);
                a[mf][1] = __float_as_uint(As[mr + gid + 8][kk + tig]);
                a[mf][2] = __float_as_uint(As[mr + gid][kk + tig + 4]);
                a[mf][3] = __float_as_uint(As[mr + gid + 8][kk + tig + 4]);
            }
#pragma unroll
            for (int nt = 0; nt < 4; nt++) {
                uint32_t b0 = __float_as_uint(Ws[kk + tig][ng * 32 + nt * 8 + gid]);
                uint32_t b1 = __float_as_uint(Ws[kk + tig + 4][ng * 32 + nt * 8 + gid]);
                mma_tf32(acc[0][nt], a[0], b0, b1);
                mma_tf32(acc[1][nt], a[1], b0, b1);
            }
        }
        __syncthreads();
        if (kc < 7) {
            stAW();
            __syncthreads();
        }
    }

#pragma unroll
    for (int mf = 0; mf < 2; mf++) {
        int r0 = row0 + m0 + mf * 16 + gid;
        int r1 = r0 + 8;
        float on0 = (r0 < NN) ? __ldg(&g_onorm[r0]) : 0.f;
        float on1 = (r1 < NN) ? __ldg(&g_onorm[r1]) : 0.f;
#pragma unroll
        for (int nt = 0; nt < 4; nt++) {
            int cp = (nh + ng * 32 + nt * 8 + tig * 2) >> 1;
            if (r0 < NN) Y[r0 * 64 + cp] = __float22bfloat162_rn(make_float2(acc[mf][nt][0] * on0, acc[mf][nt][1] * on0));
            if (r1 < NN) Y[r1 * 64 + cp] = __float22bfloat162_rn(make_float2(acc[mf][nt][2] * on1, acc[mf][nt][3] * on1));
        }
    }
}

// ---------------- TF32 GEMM: Z[N,64] = concat(h1,h2,h3) @ Wo[384,64] ----------------
// Tile M=128 x N=64, warp tile M=32 x N=32, 24 k-chunks of 16.
__global__ __launch_bounds__(256, 3) void k_gemm_z_tc(const float* __restrict__ Hc,
                                                      const float* __restrict__ Wo,
                                                      float* __restrict__ Z) {
    __shared__ float As[128][20];
    __shared__ float Ws[16][72];
    int tid = threadIdx.x;
    int warp = tid >> 5, lane = tid & 31;
    int gid = lane >> 2, tig = lane & 3;
    int m0 = (warp & 3) * 32;
    int ng = warp >> 2;
    int row0 = blockIdx.x * 128;

    float acc[2][4][4];
#pragma unroll
    for (int mf = 0; mf < 2; mf++)
#pragma unroll
        for (int i = 0; i < 4; i++)
#pragma unroll
            for (int j = 0; j < 4; j++) acc[mf][i][j] = 0.f;

    float4 pa[2], pw;

    auto ldA = [&](int kc) {
        int k0 = kc * 16;
        const float* Xb = Hc + (long long)(k0 >> 7) * NN * 128;
        int cb = k0 & 127;
#pragma unroll
        for (int u = 0; u < 2; u++) {
            int i = tid + u * 256;
            int m = i >> 2, kq = (i & 3) * 4;
            int r = row0 + m;
            pa[u] = (r < NN) ? *(const float4*)&Xb[r * 128 + cb + kq]
                             : make_float4(0.f, 0.f, 0.f, 0.f);
        }
    };
    auto ldW = [&](int kc) {
        int k0 = kc * 16;
        int k = tid >> 4, nq = (tid & 15) * 4;
        pw = *(const float4*)&Wo[(k0 + k) * 64 + nq];
    };
    auto stAW = [&]() {
#pragma unroll
        for (int u = 0; u < 2; u++) {
            int i = tid + u * 256;
            int m = i >> 2, kq = (i & 3) * 4;
            As[m][kq + 0] = to_tf32f(pa[u].x);
            As[m][kq + 1] = to_tf32f(pa[u].y);
            As[m][kq + 2] = to_tf32f(pa[u].z);
            As[m][kq + 3] = to_tf32f(pa[u].w);
        }
        int k = tid >> 4, nq = (tid & 15) * 4;
        Ws[k][nq + 0] = to_tf32f(pw.x);
        Ws[k][nq + 1] = to_tf32f(pw.y);
        Ws[k][nq + 2] = to_tf32f(pw.z);
        Ws[k][nq + 3] = to_tf32f(pw.w);
    };

    ldA(0); ldW(0);
    stAW();
    __syncthreads();

    for (int kc = 0; kc < 24; kc++) {
        if (kc < 23) { ldA(kc + 1); ldW(kc + 1); }
#pragma unroll
        for (int ks = 0; ks < 2; ks++) {
            int kk = ks * 8;
            uint32_t a[2][4];
#pragma unroll
            for (int mf = 0; mf < 2; mf++) {
                int mr = m0 + mf * 16;
                a[mf][0] = __float_as_uint(As[mr + gid][kk + tig]);
                a[mf][1] = __float_as_uint(As[mr + gid + 8][kk + tig]);
                a[mf][2] = __float_as_uint(As[mr + gid][kk + tig + 4]);
                a[mf][3] = __float_as_uint(As[mr + gid + 8][kk + tig + 4]);
            }
#pragma unroll
            for (int nt = 0; nt < 4; nt++) {
                uint32_t b0 = __float_as_uint(Ws[kk + tig][ng * 32 + nt * 8 + gid]);
                uint32_t b1 = __float_as_uint(Ws[kk + tig + 4][ng * 32 + nt * 8 + gid]);
                mma_tf32(acc[0][nt], a[0], b0, b1);
                mma_tf32(acc[1][nt], a[1], b0, b1);
            }
        }
        __syncthreads();
        if (kc < 23) {
            stAW();
            __syncthreads();
        }
    }

#pragma unroll
    for (int mf = 0; mf < 2; mf++) {
        int r0 = row0 + m0 + mf * 16 + gid;
        int r1 = r0 + 8;
#pragma unroll
        for (int nt = 0; nt < 4; nt++) {
            int c = ng * 32 + nt * 8 + tig * 2;
            if (r0 < NN) *(float2*)&Z[r0 * 64 + c] = make_float2(acc[mf][nt][0], acc[mf][nt][1]);
            if (r1 < NN) *(float2*)&Z[r1 * 64 + c] = make_float2(acc[mf][nt][2], acc[mf][nt][3]);
        }
    }
}

// ---------------- aggregation helper ----------------
__device__ __forceinline__ void bf2acc(float4& a, uint2 u) {
    __nv_bfloat162 p0 = *(__nv_bfloat162*)&u.x;
    __nv_bfloat162 p1 = *(__nv_bfloat162*)&u.y;
    float2 f0 = __bfloat1622float2(p0);
    float2 f1 = __bfloat1622float2(p1);
    a.x += f0.x; a.y += f0.y; a.z += f1.x; a.w += f1.y;
}

// ---------------- agg (all layers): Y pre-scaled; MLP=8 gather ----------------
__global__ __launch_bounds__(256) void k_agg(const __nv_bfloat162* __restrict__ Y,
                                             const float* __restrict__ b,
                                             float* __restrict__ Hout) {
    int v = (blockIdx.x * 256 + threadIdx.x) >> 5;
    if (v >= NN) return;
    int lane = threadIdx.x & 31;
    int col = lane * 4;
    int pbase = lane * 2;
    int s = g_rs[v], e = g_rs[v + 1];
    float4 a0 = make_float4(0.f, 0.f, 0.f, 0.f), a1 = a0, a2 = a0, a3 = a0;

    int j = s;
    for (; j + 8 <= e; j += 8) {
        int s0 = __ldg(&g_perm[j + 0]), s1 = __ldg(&g_perm[j + 1]);
        int s2 = __ldg(&g_perm[j + 2]), s3 = __ldg(&g_perm[j + 3]);
        int s4 = __ldg(&g_perm[j + 4]), s5 = __ldg(&g_perm[j + 5]);
        int s6 = __ldg(&g_perm[j + 6]), s7 = __ldg(&g_perm[j + 7]);
        uint2 u0 = __ldg((const uint2*)&Y[s0 * 64 + pbase]);
        uint2 u1 = __ldg((const uint2*)&Y[s1 * 64 + pbase]);
        uint2 u2 = __ldg((const uint2*)&Y[s2 * 64 + pbase]);
        uint2 u3 = __ldg((const uint2*)&Y[s3 * 64 + pbase]);
        uint2 u4 = __ldg((const uint2*)&Y[s4 * 64 + pbase]);
        uint2 u5 = __ldg((const uint2*)&Y[s5 * 64 + pbase]);
        uint2 u6 = __ldg((const uint2*)&Y[s6 * 64 + pbase]);
        uint2 u7 = __ldg((const uint2*)&Y[s7 * 64 + pbase]);
        bf2acc(a0, u0); bf2acc(a1, u1); bf2acc(a2, u2); bf2acc(a3, u3);
        bf2acc(a0, u4); bf2acc(a1, u5); bf2acc(a2, u6); bf2acc(a3, u7);
    }
    if (j + 4 <= e) {
        int s0 = __ldg(&g_perm[j + 0]), s1 = __ldg(&g_perm[j + 1]);
        int s2 = __ldg(&g_perm[j + 2]), s3 = __ldg(&g_perm[j + 3]);
        uint2 u0 = __ldg((const uint2*)&Y[s0 * 64 + pbase]);
        uint2 u1 = __ldg((const uint2*)&Y[s1 * 64 + pbase]);
        uint2 u2 = __ldg((const uint2*)&Y[s2 * 64 + pbase]);
        uint2 u3 = __ldg((const uint2*)&Y[s3 * 64 + pbase]);
        bf2acc(a0, u0); bf2acc(a1, u1); bf2acc(a2, u2); bf2acc(a3, u3);
        j += 4;
    }
    for (; j < e; j++)
        bf2acc(a0, __ldg((const uint2*)&Y[__ldg(&g_perm[j]) * 64 + pbase]));

    float in = g_inorm[v];
    float4 bb = __ldg((const float4*)&b[col]);
    float4 r;
    r.x = fmaxf((a0.x + a1.x + a2.x + a3.x) * in + bb.x, 0.f);
    r.y = fmaxf((a0.y + a1.y + a2.y + a3.y) * in + bb.y, 0.f);
    r.z = fmaxf((a0.z + a1.z + a2.z + a3.z) * in + bb.z, 0.f);
    r.w = fmaxf((a0.w + a1.w + a2.w + a3.w) * in + bb.w, 0.f);
    *(float4*)&Hout[v * 128 + col] = r;
}

// ---------------- final: warp per node, MLP=8 ----------------
__global__ __launch_bounds__(256) void k_final(const float* __restrict__ bo,
                                               float* __restrict__ Out) {
    int v = (blockIdx.x * 256 + threadIdx.x) >> 5;
    if (v >= NN) return;
    int lane = threadIdx.x & 31;
    int col = lane * 2;
    int s = g_rs[v], e = g_rs[v + 1];
    float2 a0 = make_float2(0.f, 0.f), a1 = a0, a2 = a0, a3 = a0;
    int j = s;
    for (; j + 8 <= e; j += 8) {
        int s0 = __ldg(&g_perm[j + 0]), s1 = __ldg(&g_perm[j + 1]);
        int s2 = __ldg(&g_perm[j + 2]), s3 = __ldg(&g_perm[j + 3]);
        int s4 = __ldg(&g_perm[j + 4]), s5 = __ldg(&g_perm[j + 5]);
        int s6 = __ldg(&g_perm[j + 6]), s7 = __ldg(&g_perm[j + 7]);
        float2 v0 = __ldg((const float2*)&g_z[s0 * 64 + col]);
        float2 v1 = __ldg((const float2*)&g_z[s1 * 64 + col]);
        float2 v2 = __ldg((const float2*)&g_z[s2 * 64 + col]);
        float2 v3 = __ldg((const float2*)&g_z[s3 * 64 + col]);
        float2 v4 = __ldg((const float2*)&g_z[s4 * 64 + col]);
        float2 v5 = __ldg((const float2*)&g_z[s5 * 64 + col]);
        float2 v6 = __ldg((const float2*)&g_z[s6 * 64 + col]);
        float2 v7 = __ldg((const float2*)&g_z[s7 * 64 + col]);
        a0.x += v0.x + v4.x; a0.y += v0.y + v4.y;
        a1.x += v1.x + v5.x; a1.y += v1.y + v5.y;
        a2.x += v2.x + v6.x; a2.y += v2.y + v6.y;
        a3.x += v3.x + v7.x; a3.y += v3.y + v7.y;
    }
    if (j + 4 <= e) {
        int s0 = __ldg(&g_perm[j + 0]), s1 = __ldg(&g_perm[j + 1]);
        int s2 = __ldg(&g_perm[j + 2]), s3 = __ldg(&g_perm[j + 3]);
        float2 v0 = __ldg((const float2*)&g_z[s0 * 64 + col]);
        float2 v1 = __ldg((const float2*)&g_z[s1 * 64 + col]);
        float2 v2 = __ldg((const float2*)&g_z[s2 * 64 + col]);
        float2 v3 = __ldg((const float2*)&g_z[s3 * 64 + col]);
        a0.x += v0.x; a0.y += v0.y;
        a1.x += v1.x; a1.y += v1.y;
        a2.x += v2.x; a2.y += v2.y;
        a3.x += v3.x; a3.y += v3.y;
        j += 4;
    }
    for (; j < e; j++) {
        float2 v0 = __ldg((const float2*)&g_z[__ldg(&g_perm[j]) * 64 + col]);
        a0.x += v0.x; a0.y += v0.y;
    }
    float2 bb = __ldg((const float2*)&bo[col]);
    Out[v * 64 + col + 0] = (a0.x + a1.x) + (a2.x + a3.x) + bb.x;
    Out[v * 64 + col + 1] = (a0.y + a1.y) + (a2.y + a3.y) + bb.y;
}

// ---------------- host ----------------
extern "C" void kernel_launch(void* const* d_in, const int* in_sizes, int n_in,
                              void* d_out, int out_size) {
    const float* feats = (const float*)d_in[0];
    const int*   src   = (const int*)d_in[1];
    const int*   dst   = (const int*)d_in[2];
    const float* W0    = (const float*)d_in[3];
    const float* b0    = (const float*)d_in[4];
    const float* W1    = (const float*)d_in[5];
    const float* b1    = (const float*)d_in[6];
    const float* W2    = (const float*)d_in[7];
    const float* b2    = (const float*)d_in[8];
    const float* Wo    = (const float*)d_in[9];
    const float* bo    = (const float*)d_in[10];
    float* out = (float*)d_out;

    void *p_deg, *p_h, *p_y, *p_z;
    cudaGetSymbolAddress(&p_deg, g_deg);
    cudaGetSymbolAddress(&p_h, g_h);
    cudaGetSymbolAddress(&p_y, g_y);
    cudaGetSymbolAddress(&p_z, g_z);
    float* hbuf = (float*)p_h;
    __nv_bfloat162* ybuf = (__nv_bfloat162*)p_y;
    float* zbuf = (float*)p_z;

    cudaMemsetAsync(p_deg, 0, 2 * NN * sizeof(int));

    dim3 gconv((NN + 127) / 128, 2);    // 782 x 2
    int gz = (NN + 127) / 128;          // 782
    int ab = (NN * 32 + 255) / 256;
    int eb = (NE + 255) / 256;

    k_degree<<<eb, 256>>>(src, dst);                          // 1
    k_scan<<<1, 1024>>>();                                    // 2
    k_build<<<eb, 256>>>(src, dst);                           // 3
    k_gemm_conv_tc<<<gconv, 256>>>(feats, W0, ybuf);          // 4  <- ncu window
    k_agg<<<ab, 256>>>(ybuf, b0, hbuf);
    k_gemm_conv_tc<<<gconv, 256>>>(hbuf, W1, ybuf);
    k_agg<<<ab, 256>>>(ybuf, b1, hbuf + (long long)NN * 128);
    k_gemm_conv_tc<<<gconv, 256>>>(hbuf + 1ll * NN * 128, W2, ybuf);
    k_agg<<<ab, 256>>>(ybuf, b2, hbuf + 2ll * NN * 128);
    k_gemm_z_tc<<<gz, 256>>>(hbuf, Wo, zbuf);
    k_final<<<ab, 256>>>(bo, out);
}

// round 17
// speedup vs baseline: 1.0780x; 1.0111x over previous
#include <cuda_runtime.h>
#include <cuda_bf16.h>
#include <cstdint>

#define NN 100000
#define NE 1600000
#define FH 128
#define CC 64
#define GBC 1564          // gemm blocks in fused kernel: ceil(NN/128)*2
#define BLDB 6250         // build blocks: ceil(NE/256)

// ---------------- scratch ----------------
__device__ float g_h[3ll * NN * FH];                 // h1,h2,h3 (fp32)
__device__ __nv_bfloat162 g_y[(long long)NN * 64];   // Y packed bf16x2 (pre-scaled by onorm)
__device__ float g_z[(long long)NN * CC];
__device__ __align__(16) float g_onorm[NN];
__device__ __align__(16) float g_inorm[NN];
__device__ __align__(16) int   g_deg[2 * NN];        // [0,NN)=indeg, [NN,2NN)=outdeg
__device__ __align__(16) int   g_rs[NN + 4];
__device__ __align__(16) int   g_cur[NN + 4];
__device__ __align__(16) int   g_perm[NE];

// ---------------- helpers ----------------
__device__ __forceinline__ uint32_t to_tf32(float x) {
    uint32_t y;
    asm("cvt.rna.tf32.f32 %0, %1;" : "=r"(y) : "f"(x));
    return y;
}
__device__ __forceinline__ float to_tf32f(float x) {
    return __uint_as_float(to_tf32(x));
}

__device__ __forceinline__ void mma_tf32(float* c, const uint32_t* a, uint32_t b0, uint32_t b1) {
    asm volatile(
        "mma.sync.aligned.m16n8k8.row.col.f32.tf32.tf32.f32 "
        "{%0,%1,%2,%3}, {%4,%5,%6,%7}, {%8,%9}, {%0,%1,%2,%3};"
        : "+f"(c[0]), "+f"(c[1]), "+f"(c[2]), "+f"(c[3])
        : "r"(a[0]), "r"(a[1]), "r"(a[2]), "r"(a[3]), "r"(b0), "r"(b1));
}

// ---------------- graph prep ----------------
__global__ void k_degree(const int* __restrict__ src, const int* __restrict__ dst) {
    int e = blockIdx.x * blockDim.x + threadIdx.x;
    if (e < NE) {
        atomicAdd(&g_deg[NN + src[e]], 1);   // outdeg
        atomicAdd(&g_deg[dst[e]], 1);        // indeg
    }
}

__global__ __launch_bounds__(1024) void k_scan() {
    __shared__ int sums[1024];
    int tid = threadIdx.x;
    const int chunk = 100;
    int b = tid * chunk;
    int s = 0;
    if (b < NN) {
        const int4* p = (const int4*)(g_deg + b);
#pragma unroll 5
        for (int i = 0; i < 25; i++) {
            int4 v = p[i];
            s += v.x + v.y + v.z + v.w;
        }
    }
    sums[tid] = s;
    __syncthreads();
    for (int off = 1; off < 1024; off <<= 1) {
        int v = (tid >= off) ? sums[tid - off] : 0;
        __syncthreads();
        sums[tid] += v;
        __syncthreads();
    }
    int run = (tid == 0) ? 0 : sums[tid - 1];
    if (b < NN) {
        const int4* pi = (const int4*)(g_deg + b);
        const int4* po = (const int4*)(g_deg + NN + b);
        for (int i = 0; i < 25; i++) {
            int4 di = pi[i];
            int4 dq = po[i];
            int4 r4;
            r4.x = run; run += di.x;
            r4.y = run; run += di.y;
            r4.z = run; run += di.z;
            r4.w = run; run += di.w;
            *(int4*)(g_rs + b + i * 4) = r4;
            *(int4*)(g_cur + b + i * 4) = r4;
            float4 in4, on4;
            in4.x = di.x > 0 ? rsqrtf((float)di.x) : 0.f;
            in4.y = di.y > 0 ? rsqrtf((float)di.y) : 0.f;
            in4.z = di.z > 0 ? rsqrtf((float)di.z) : 0.f;
            in4.w = di.w > 0 ? rsqrtf((float)di.w) : 0.f;
            on4.x = dq.x > 0 ? rsqrtf((float)dq.x) : 0.f;
            on4.y = dq.y > 0 ? rsqrtf((float)dq.y) : 0.f;
            on4.z = dq.z > 0 ? rsqrtf((float)dq.z) : 0.f;
            on4.w = dq.w > 0 ? rsqrtf((float)dq.w) : 0.f;
            *(float4*)(g_inorm + b + i * 4) = in4;
            *(float4*)(g_onorm + b + i * 4) = on4;
        }
        if (b + chunk == NN) g_rs[NN] = run;
    }
}

// ---------------- TF32 conv GEMM body: Y[N,128] = (X @ W) .* onorm ----------------
// Tile M=128 x N=64 (by = N-half). Warp tile M=32 x N=32. K-chunks of 16.
__device__ __forceinline__ void gemm_conv_body(const float* __restrict__ X,
                                               const float* __restrict__ W,
                                               __nv_bfloat162* __restrict__ Y,
                                               int bx, int by) {
    __shared__ float As[128][20];   // [m][k] stride 20 -> conflict-free frag loads
    __shared__ float Ws[16][72];    // [k][n] stride 72 -> conflict-free frag loads
    int tid = threadIdx.x;
    int warp = tid >> 5, lane = tid & 31;
    int gid = lane >> 2, tig = lane & 3;
    int m0 = (warp & 3) * 32;
    int ng = warp >> 2;
    int row0 = bx * 128;
    int nh = by * 64;

    float acc[2][4][4];
#pragma unroll
    for (int mf = 0; mf < 2; mf++)
#pragma unroll
        for (int i = 0; i < 4; i++)
#pragma unroll
            for (int j = 0; j < 4; j++) acc[mf][i][j] = 0.f;

    float4 pa[2], pw;

    auto ldA = [&](int k0) {
#pragma unroll
        for (int u = 0; u < 2; u++) {
            int i = tid + u * 256;
            int m = i >> 2, kq = (i & 3) * 4;
            int r = row0 + m;
            pa[u] = (r < NN) ? *(const float4*)&X[r * 128 + k0 + kq]
                             : make_float4(0.f, 0.f, 0.f, 0.f);
        }
    };
    auto ldW = [&](int k0) {
        int k = tid >> 4, nq = (tid & 15) * 4;
        pw = *(const float4*)&W[(k0 + k) * 128 + nh + nq];
    };
    auto stAW = [&]() {
#pragma unroll
        for (int u = 0; u < 2; u++) {
            int i = tid + u * 256;
            int m = i >> 2, kq = (i & 3) * 4;
            As[m][kq + 0] = to_tf32f(pa[u].x);
            As[m][kq + 1] = to_tf32f(pa[u].y);
            As[m][kq + 2] = to_tf32f(pa[u].z);
            As[m][kq + 3] = to_tf32f(pa[u].w);
        }
        int k = tid >> 4, nq = (tid & 15) * 4;
        Ws[k][nq + 0] = to_tf32f(pw.x);
        Ws[k][nq + 1] = to_tf32f(pw.y);
        Ws[k][nq + 2] = to_tf32f(pw.z);
        Ws[k][nq + 3] = to_tf32f(pw.w);
    };

    ldA(0); ldW(0);
    stAW();
    __syncthreads();

    for (int kc = 0; kc < 8; kc++) {
        if (kc < 7) { ldA((kc + 1) * 16); ldW((kc + 1) * 16); }
#pragma unroll
        for (int ks = 0; ks < 2; ks++) {
            int kk = ks * 8;
            uint32_t a[2][4];
#pragma unroll
            for (int mf = 0; mf < 2; mf++) {
                int mr = m0 + mf * 16;
                a[mf][0] = __float_as_uint(As[mr + gid][kk + tig]);
                a[mf][1] = __float_as_uint(As[mr + gid + 8][kk + tig]);
                a[mf][2] = __float_as_uint(As[mr + gid][kk + tig + 4]);
                a[mf][3] = __float_as_uint(As[mr + gid + 8][kk + tig + 4]);
            }
#pragma unroll
            for (int nt = 0; nt < 4; nt++) {
                uint32_t b0 = __float_as_uint(Ws[kk + tig][ng * 32 + nt * 8 + gid]);
                uint32_t b1 = __float_as_uint(Ws[kk + tig + 4][ng * 32 + nt * 8 + gid]);
                mma_tf32(acc[0][nt], a[0], b0, b1);
                mma_tf32(acc[1][nt], a[1], b0, b1);
            }
        }
        __syncthreads();
        if (kc < 7) {
            stAW();
            __syncthreads();
        }
    }

#pragma unroll
    for (int mf = 0; mf < 2; mf++) {
        int r0 = row0 + m0 + mf * 16 + gid;
        int r1 = r0 + 8;
        float on0 = (r0 < NN) ? __ldg(&g_onorm[r0]) : 0.f;
        float on1 = (r1 < NN) ? __ldg(&g_onorm[r1]) : 0.f;
#pragma unroll
        for (int nt = 0; nt < 4; nt++) {
            int cp = (nh + ng * 32 + nt * 8 + tig * 2) >> 1;
            if (r0 < NN) Y[r0 * 64 + cp] = __float22bfloat162_rn(make_float2(acc[mf][nt][0] * on0, acc[mf][nt][1] * on0));
            if (r1 < NN) Y[r1 * 64 + cp] = __float22bfloat162_rn(make_float2(acc[mf][nt][2] * on1, acc[mf][nt][3] * on1));
        }
    }
}

// ---------------- fused: layer-1 GEMM + CSR build (both depend only on scan) ----------------
__global__ __launch_bounds__(256, 3) void k_fused_bg(const int* __restrict__ src,
                                                     const int* __restrict__ dst,
                                                     const float* __restrict__ X,
                                                     const float* __restrict__ W,
                                                     __nv_bfloat162* __restrict__ Y) {
    if (blockIdx.x < GBC) {
        gemm_conv_body(X, W, Y, blockIdx.x >> 1, blockIdx.x & 1);
    } else {
        int e = (blockIdx.x - GBC) * 256 + threadIdx.x;
        if (e < NE) {
            int p = atomicAdd(&g_cur[dst[e]], 1);
            g_perm[p] = src[e];
        }
    }
}

// ---------------- plain conv GEMM (layers 2,3) ----------------
__global__ __launch_bounds__(256, 3) void k_gemm_conv_tc(const float* __restrict__ X,
                                                         const float* __restrict__ W,
                                                         __nv_bfloat162* __restrict__ Y) {
    gemm_conv_body(X, W, Y, blockIdx.x, blockIdx.y);
}

// ---------------- TF32 GEMM: Z[N,64] = concat(h1,h2,h3) @ Wo[384,64] ----------------
__global__ __launch_bounds__(256, 3) void k_gemm_z_tc(const float* __restrict__ Hc,
                                                      const float* __restrict__ Wo,
                                                      float* __restrict__ Z) {
    __shared__ float As[128][20];
    __shared__ float Ws[16][72];
    int tid = threadIdx.x;
    int warp = tid >> 5, lane = tid & 31;
    int gid = lane >> 2, tig = lane & 3;
    int m0 = (warp & 3) * 32;
    int ng = warp >> 2;
    int row0 = blockIdx.x * 128;

    float acc[2][4][4];
#pragma unroll
    for (int mf = 0; mf < 2; mf++)
#pragma unroll
        for (int i = 0; i < 4; i++)
#pragma unroll
            for (int j = 0; j < 4; j++) acc[mf][i][j] = 0.f;

    float4 pa[2], pw;

    auto ldA = [&](int kc) {
        int k0 = kc * 16;
        const float* Xb = Hc + (long long)(k0 >> 7) * NN * 128;
        int cb = k0 & 127;
#pragma unroll
        for (int u = 0; u < 2; u++) {
            int i = tid + u * 256;
            int m = i >> 2, kq = (i & 3) * 4;
            int r = row0 + m;
            pa[u] = (r < NN) ? *(const float4*)&Xb[r * 128 + cb + kq]
                             : make_float4(0.f, 0.f, 0.f, 0.f);
        }
    };
    auto ldW = [&](int kc) {
        int k0 = kc * 16;
        int k = tid >> 4, nq = (tid & 15) * 4;
        pw = *(const float4*)&Wo[(k0 + k) * 64 + nq];
    };
    auto stAW = [&]() {
#pragma unroll
        for (int u = 0; u < 2; u++) {
            int i = tid + u * 256;
            int m = i >> 2, kq = (i & 3) * 4;
            As[m][kq + 0] = to_tf32f(pa[u].x);
            As[m][kq + 1] = to_tf32f(pa[u].y);
            As[m][kq + 2] = to_tf32f(pa[u].z);
            As[m][kq + 3] = to_tf32f(pa[u].w);
        }
        int k = tid >> 4, nq = (tid & 15) * 4;
        Ws[k][nq + 0] = to_tf32f(pw.x);
        Ws[k][nq + 1] = to_tf32f(pw.y);
        Ws[k][nq + 2] = to_tf32f(pw.z);
        Ws[k][nq + 3] = to_tf32f(pw.w);
    };

    ldA(0); ldW(0);
    stAW();
    __syncthreads();

    for (int kc = 0; kc < 24; kc++) {
        if (kc < 23) { ldA(kc + 1); ldW(kc + 1); }
#pragma unroll
        for (int ks = 0; ks < 2; ks++) {
            int kk = ks * 8;
            uint32_t a[2][4];
#pragma unroll
            for (int mf = 0; mf < 2; mf++) {
                int mr = m0 + mf * 16;
                a[mf][0] = __float_as_uint(As[mr + gid][kk + tig]);
                a[mf][1] = __float_as_uint(As[mr + gid + 8][kk + tig]);
                a[mf][2] = __float_as_uint(As[mr + gid][kk + tig + 4]);
                a[mf][3] = __float_as_uint(As[mr + gid + 8][kk + tig + 4]);
            }
#pragma unroll
            for (int nt = 0; nt < 4; nt++) {
                uint32_t b0 = __float_as_uint(Ws[kk + tig][ng * 32 + nt * 8 + gid]);
                uint32_t b1 = __float_as_uint(Ws[kk + tig + 4][ng * 32 + nt * 8 + gid]);
                mma_tf32(acc[0][nt], a[0], b0, b1);
                mma_tf32(acc[1][nt], a[1], b0, b1);
            }
        }
        __syncthreads();
        if (kc < 23) {
            stAW();
            __syncthreads();
        }
    }

#pragma unroll
    for (int mf = 0; mf < 2; mf++) {
        int r0 = row0 + m0 + mf * 16 + gid;
        int r1 = r0 + 8;
#pragma unroll
        for (int nt = 0; nt < 4; nt++) {
            int c = ng * 32 + nt * 8 + tig * 2;
            if (r0 < NN) *(float2*)&Z[r0 * 64 + c] = make_float2(acc[mf][nt][0], acc[mf][nt][1]);
            if (r1 < NN) *(float2*)&Z[r1 * 64 + c] = make_float2(acc[mf][nt][2], acc[mf][nt][3]);
        }
    }
}

// ---------------- aggregation helper ----------------
__device__ __forceinline__ void bf2acc(float4& a, uint2 u) {
    __nv_bfloat162 p0 = *(__nv_bfloat162*)&u.x;
    __nv_bfloat162 p1 = *(__nv_bfloat162*)&u.y;
    float2 f0 = __bfloat1622float2(p0);
    float2 f1 = __bfloat1622float2(p1);
    a.x += f0.x; a.y += f0.y; a.z += f1.x; a.w += f1.y;
}

// ---------------- agg (all layers): Y pre-scaled; MLP=8 gather ----------------
__global__ __launch_bounds__(256) void k_agg(const __nv_bfloat162* __restrict__ Y,
                                             const float* __restrict__ b,
                                             float* __restrict__ Hout) {
    int v = (blockIdx.x * 256 + threadIdx.x) >> 5;
    if (v >= NN) return;
    int lane = threadIdx.x & 31;
    int col = lane * 4;
    int pbase = lane * 2;
    int s = g_rs[v], e = g_rs[v + 1];
    float4 a0 = make_float4(0.f, 0.f, 0.f, 0.f), a1 = a0, a2 = a0, a3 = a0;

    int j = s;
    for (; j + 8 <= e; j += 8) {
        int s0 = __ldg(&g_perm[j + 0]), s1 = __ldg(&g_perm[j + 1]);
        int s2 = __ldg(&g_perm[j + 2]), s3 = __ldg(&g_perm[j + 3]);
        int s4 = __ldg(&g_perm[j + 4]), s5 = __ldg(&g_perm[j + 5]);
        int s6 = __ldg(&g_perm[j + 6]), s7 = __ldg(&g_perm[j + 7]);
        uint2 u0 = __ldg((const uint2*)&Y[s0 * 64 + pbase]);
        uint2 u1 = __ldg((const uint2*)&Y[s1 * 64 + pbase]);
        uint2 u2 = __ldg((const uint2*)&Y[s2 * 64 + pbase]);
        uint2 u3 = __ldg((const uint2*)&Y[s3 * 64 + pbase]);
        uint2 u4 = __ldg((const uint2*)&Y[s4 * 64 + pbase]);
        uint2 u5 = __ldg((const uint2*)&Y[s5 * 64 + pbase]);
        uint2 u6 = __ldg((const uint2*)&Y[s6 * 64 + pbase]);
        uint2 u7 = __ldg((const uint2*)&Y[s7 * 64 + pbase]);
        bf2acc(a0, u0); bf2acc(a1, u1); bf2acc(a2, u2); bf2acc(a3, u3);
        bf2acc(a0, u4); bf2acc(a1, u5); bf2acc(a2, u6); bf2acc(a3, u7);
    }
    if (j + 4 <= e) {
        int s0 = __ldg(&g_perm[j + 0]), s1 = __ldg(&g_perm[j + 1]);
        int s2 = __ldg(&g_perm[j + 2]), s3 = __ldg(&g_perm[j + 3]);
        uint2 u0 = __ldg((const uint2*)&Y[s0 * 64 + pbase]);
        uint2 u1 = __ldg((const uint2*)&Y[s1 * 64 + pbase]);
        uint2 u2 = __ldg((const uint2*)&Y[s2 * 64 + pbase]);
        uint2 u3 = __ldg((const uint2*)&Y[s3 * 64 + pbase]);
        bf2acc(a0, u0); bf2acc(a1, u1); bf2acc(a2, u2); bf2acc(a3, u3);
        j += 4;
    }
    for (; j < e; j++)
        bf2acc(a0, __ldg((const uint2*)&Y[__ldg(&g_perm[j]) * 64 + pbase]));

    float in = g_inorm[v];
    float4 bb = __ldg((const float4*)&b[col]);
    float4 r;
    r.x = fmaxf((a0.x + a1.x + a2.x + a3.x) * in + bb.x, 0.f);
    r.y = fmaxf((a0.y + a1.y + a2.y + a3.y) * in + bb.y, 0.f);
    r.z = fmaxf((a0.z + a1.z + a2.z + a3.z) * in + bb.z, 0.f);
    r.w = fmaxf((a0.w + a1.w + a2.w + a3.w) * in + bb.w, 0.f);
    *(float4*)&Hout[v * 128 + col] = r;
}

// ---------------- final: warp per node, MLP=8 ----------------
__global__ __launch_bounds__(256) void k_final(const float* __restrict__ bo,
                                               float* __restrict__ Out) {
    int v = (blockIdx.x * 256 + threadIdx.x) >> 5;
    if (v >= NN) return;
    int lane = threadIdx.x & 31;
    int col = lane * 2;
    int s = g_rs[v], e = g_rs[v + 1];
    float2 a0 = make_float2(0.f, 0.f), a1 = a0, a2 = a0, a3 = a0;
    int j = s;
    for (; j + 8 <= e; j += 8) {
        int s0 = __ldg(&g_perm[j + 0]), s1 = __ldg(&g_perm[j + 1]);
        int s2 = __ldg(&g_perm[j + 2]), s3 = __ldg(&g_perm[j + 3]);
        int s4 = __ldg(&g_perm[j + 4]), s5 = __ldg(&g_perm[j + 5]);
        int s6 = __ldg(&g_perm[j + 6]), s7 = __ldg(&g_perm[j + 7]);
        float2 v0 = __ldg((const float2*)&g_z[s0 * 64 + col]);
        float2 v1 = __ldg((const float2*)&g_z[s1 * 64 + col]);
        float2 v2 = __ldg((const float2*)&g_z[s2 * 64 + col]);
        float2 v3 = __ldg((const float2*)&g_z[s3 * 64 + col]);
        float2 v4 = __ldg((const float2*)&g_z[s4 * 64 + col]);
        float2 v5 = __ldg((const float2*)&g_z[s5 * 64 + col]);
        float2 v6 = __ldg((const float2*)&g_z[s6 * 64 + col]);
        float2 v7 = __ldg((const float2*)&g_z[s7 * 64 + col]);
        a0.x += v0.x + v4.x; a0.y += v0.y + v4.y;
        a1.x += v1.x + v5.x; a1.y += v1.y + v5.y;
        a2.x += v2.x + v6.x; a2.y += v2.y + v6.y;
        a3.x += v3.x + v7.x; a3.y += v3.y + v7.y;
    }
    if (j + 4 <= e) {
        int s0 = __ldg(&g_perm[j + 0]), s1 = __ldg(&g_perm[j + 1]);
        int s2 = __ldg(&g_perm[j + 2]), s3 = __ldg(&g_perm[j + 3]);
        float2 v0 = __ldg((const float2*)&g_z[s0 * 64 + col]);
        float2 v1 = __ldg((const float2*)&g_z[s1 * 64 + col]);
        float2 v2 = __ldg((const float2*)&g_z[s2 * 64 + col]);
        float2 v3 = __ldg((const float2*)&g_z[s3 * 64 + col]);
        a0.x += v0.x; a0.y += v0.y;
        a1.x += v1.x; a1.y += v1.y;
        a2.x += v2.x; a2.y += v2.y;
        a3.x += v3.x; a3.y += v3.y;
        j += 4;
    }
    for (; j < e; j++) {
        float2 v0 = __ldg((const float2*)&g_z[__ldg(&g_perm[j]) * 64 + col]);
        a0.x += v0.x; a0.y += v0.y;
    }
    float2 bb = __ldg((const float2*)&bo[col]);
    Out[v * 64 + col + 0] = (a0.x + a1.x) + (a2.x + a3.x) + bb.x;
    Out[v * 64 + col + 1] = (a0.y + a1.y) + (a2.y + a3.y) + bb.y;
}

// ---------------- host ----------------
extern "C" void kernel_launch(void* const* d_in, const int* in_sizes, int n_in,
                              void* d_out, int out_size) {
    const float* feats = (const float*)d_in[0];
    const int*   src   = (const int*)d_in[1];
    const int*   dst   = (const int*)d_in[2];
    const float* W0    = (const float*)d_in[3];
    const float* b0    = (const float*)d_in[4];
    const float* W1    = (const float*)d_in[5];
    const float* b1    = (const float*)d_in[6];
    const float* W2    = (const float*)d_in[7];
    const float* b2    = (const float*)d_in[8];
    const float* Wo    = (const float*)d_in[9];
    const float* bo    = (const float*)d_in[10];
    float* out = (float*)d_out;

    void *p_deg, *p_h, *p_y, *p_z;
    cudaGetSymbolAddress(&p_deg, g_deg);
    cudaGetSymbolAddress(&p_h, g_h);
    cudaGetSymbolAddress(&p_y, g_y);
    cudaGetSymbolAddress(&p_z, g_z);
    float* hbuf = (float*)p_h;
    __nv_bfloat162* ybuf = (__nv_bfloat162*)p_y;
    float* zbuf = (float*)p_z;

    cudaMemsetAsync(p_deg, 0, 2 * NN * sizeof(int));

    dim3 gconv((NN + 127) / 128, 2);    // 782 x 2
    int gz = (NN + 127) / 128;          // 782
    int ab = (NN * 32 + 255) / 256;
    int eb = (NE + 255) / 256;

    k_degree<<<eb, 256>>>(src, dst);                          // 1
    k_scan<<<1, 1024>>>();                                    // 2
    k_fused_bg<<<GBC + BLDB, 256>>>(src, dst, feats, W0, ybuf); // 3: gemm1 + build overlapped
    k_agg<<<ab, 256>>>(ybuf, b0, hbuf);                       // 4  <- ncu window
    k_gemm_conv_tc<<<gconv, 256>>>(hbuf, W1, ybuf);
    k_agg<<<ab, 256>>>(ybuf, b1, hbuf + (long long)NN * 128);
    k_gemm_conv_tc<<<gconv, 256>>>(hbuf + 1ll * NN * 128, W2, ybuf);
    k_agg<<<ab, 256>>>(ybuf, b2, hbuf + 2ll * NN * 128);
    k_gemm_z_tc<<<gz, 256>>>(hbuf, Wo, zbuf);
    k_final<<<ab, 256>>>(bo, out);
}